// round 12
// baseline (speedup 1.0000x reference)
#include <cuda_runtime.h>
#include <cuda_fp16.h>
#include <cstdint>

#define EMB 128
#define MAX_NODES 100000
#define MAX_EDGES 1600000
#define SSTRIDE 132   // padded smem row stride (floats): conflict-free frag reads

// ---------------- scratch (static device globals: allocation-guard safe) ----
__device__ __half g_bufA[(size_t)MAX_NODES * EMB];
__device__ __half g_bufB[(size_t)MAX_NODES * EMB];
__device__ int    g_csrws[MAX_NODES + 64];   // cnt | stat(52) | ticket | done
__device__ int    g_rs[MAX_NODES + 1];
__device__ int    g_cur[MAX_NODES];
__device__ float  g_inv[MAX_NODES];
__device__ int2   g_scv[MAX_EDGES];          // (col<<7 element offset, val bits)
__device__ uint4  g_wfrag[8 * 8 * 32];       // fp16 B-fragments, j-pair packed (32 KB)

__device__ __forceinline__ float sigmoid_t(float z) {
    float t;
    asm("tanh.approx.f32 %0, %1;" : "=f"(t) : "f"(0.5f * z));
    return fmaf(0.5f, t, 0.5f);
}

__device__ __forceinline__ unsigned int h2u(__half2 h) {
    return *reinterpret_cast<unsigned int*>(&h);
}

// ---------------- hist + W-fragment transpose (fused) ------------------------
__global__ void hist_wtrans_kernel(const int* __restrict__ rows,
                                   int* __restrict__ cnt, int nnz,
                                   const float* __restrict__ W,
                                   uint4* __restrict__ wfrag) {
    if (blockIdx.x < 8) {
        int id = blockIdx.x * 256 + threadIdx.x;    // 0..2047
        int lane = id & 31;
        int jp = (id >> 5) & 7;
        int kk = id >> 8;
        int g  = lane >> 2;
        int tg = lane & 3;
        int k0 = kk * 16 + tg * 2;
        int col0 = (2 * jp)     * 8 + g;
        int col1 = (2 * jp + 1) * 8 + g;
        __half2 b0j0 = __floats2half2_rn(W[(size_t)k0       * EMB + col0], W[(size_t)(k0 + 1) * EMB + col0]);
        __half2 b1j0 = __floats2half2_rn(W[(size_t)(k0 + 8) * EMB + col0], W[(size_t)(k0 + 9) * EMB + col0]);
        __half2 b0j1 = __floats2half2_rn(W[(size_t)k0       * EMB + col1], W[(size_t)(k0 + 1) * EMB + col1]);
        __half2 b1j1 = __floats2half2_rn(W[(size_t)(k0 + 8) * EMB + col1], W[(size_t)(k0 + 9) * EMB + col1]);
        uint4 v;
        v.x = h2u(b0j0); v.y = h2u(b1j0);
        v.z = h2u(b0j1); v.w = h2u(b1j1);
        wfrag[id] = v;
    } else {
        int e = (blockIdx.x - 8) * 256 + threadIdx.x;
        if (e < nnz) atomicAdd(&cnt[rows[e]], 1);
    }
}

// ---------------- single-pass decoupled-lookback scan (self-cleaning) --------
__global__ void scan_kernel(int* __restrict__ cnt,
                            int* __restrict__ rs, int* __restrict__ cur,
                            unsigned long long* __restrict__ stat,
                            int* __restrict__ ticket, int* __restrict__ done,
                            int n) {
    __shared__ int sbid;
    __shared__ int warpsum[32];
    __shared__ int sprefix;
    int t = threadIdx.x;
    if (t == 0) sbid = atomicAdd(ticket, 1);
    __syncthreads();
    int bid = sbid;

    int base = bid * 4096 + t * 4;
    int4 c = make_int4(0, 0, 0, 0);
    if (base + 3 < n) {
        c = *reinterpret_cast<const int4*>(cnt + base);
        *reinterpret_cast<int4*>(cnt + base) = make_int4(0, 0, 0, 0);
    } else {
        if (base     < n) { c.x = cnt[base];     cnt[base]     = 0; }
        if (base + 1 < n) { c.y = cnt[base + 1]; cnt[base + 1] = 0; }
        if (base + 2 < n) { c.z = cnt[base + 2]; cnt[base + 2] = 0; }
        if (base + 3 < n) { c.w = cnt[base + 3]; cnt[base + 3] = 0; }
    }
    int tot = c.x + c.y + c.z + c.w;
    int lane = t & 31, wid = t >> 5;
    int inc = tot;
#pragma unroll
    for (int o = 1; o < 32; o <<= 1) {
        int u = __shfl_up_sync(0xFFFFFFFFu, inc, o);
        if (lane >= o) inc += u;
    }
    if (lane == 31) warpsum[wid] = inc;
    __syncthreads();
    if (wid == 0) {
        int w = warpsum[lane];
#pragma unroll
        for (int o = 1; o < 32; o <<= 1) {
            int u = __shfl_up_sync(0xFFFFFFFFu, w, o);
            if (lane >= o) w += u;
        }
        warpsum[lane] = w;
    }
    __syncthreads();
    int blocktot = warpsum[31];
    int excl = inc - tot + (wid ? warpsum[wid - 1] : 0);

    if (t == 0) {
        if (bid == 0) {
            atomicExch(&stat[0], (2ull << 32) | (unsigned)blocktot);
            sprefix = 0;
        } else {
            atomicExch(&stat[bid], (1ull << 32) | (unsigned)blocktot);
            int pre = 0;
            for (int i = bid - 1; i >= 0; i--) {
                unsigned long long s;
                do { s = atomicAdd(&stat[i], 0ull); } while ((s >> 32) == 0ull);
                pre += (int)(unsigned)s;
                if ((s >> 32) == 2ull) break;
            }
            atomicExch(&stat[bid], (2ull << 32) | (unsigned)(pre + blocktot));
            sprefix = pre;
        }
    }
    __syncthreads();
    int prefix = sprefix;

    int v0 = excl + prefix;
    if (base     < n) { rs[base]     = v0;                   cur[base]     = v0; }
    if (base + 1 < n) { rs[base + 1] = v0 + c.x;             cur[base + 1] = v0 + c.x; }
    if (base + 2 < n) { rs[base + 2] = v0 + c.x + c.y;       cur[base + 2] = v0 + c.x + c.y; }
    if (base + 3 < n) { rs[base + 3] = v0 + c.x + c.y + c.z; cur[base + 3] = v0 + c.x + c.y + c.z; }
    if (bid == gridDim.x - 1 && t == 1023) rs[n] = prefix + blocktot;

    __syncthreads();
    if (t == 0) {
        int d = atomicAdd(done, 1);
        if (d == (int)gridDim.x - 1) {
            for (int i = 0; i < (int)gridDim.x; i++) stat[i] = 0ull;
            *ticket = 0;
            *done = 0;
        }
    }
}

__global__ void scatter_kernel(const int* __restrict__ rows,
                               const int* __restrict__ cols,
                               const float* __restrict__ vals,
                               int* __restrict__ cur,
                               int2* __restrict__ scv, int nnz) {
    int e = blockIdx.x * 256 + threadIdx.x;
    if (e >= nnz) return;
    int p = atomicAdd(&cur[rows[e]], 1);
    scv[p] = make_int2(cols[e] << 7, __float_as_int(vals[e]));   // element offset
}

// ---------------- self-gating: fp16 warp-MMA, 64-row tiles ------------------
__global__ void __launch_bounds__(256)
gate_mma_kernel(const float* __restrict__ emb,
                const uint4* __restrict__ wfrag,
                const float* __restrict__ b,
                __half* __restrict__ u,
                float* __restrict__ acc,
                int n) {
    extern __shared__ float sA[];              // [64][SSTRIDE]
    __shared__ float sB[EMB];
    const int tx = threadIdx.x;
    const int warpid = tx >> 5;
    const int lane = tx & 31;
    const int row0 = blockIdx.x * 64;

    for (int i = tx; i < 64 * 32; i += 256) {
        int r = i >> 5;
        int cc = (i & 31) * 4;
        float4 v = make_float4(0.f, 0.f, 0.f, 0.f);
        if (row0 + r < n)
            v = *reinterpret_cast<const float4*>(emb + (size_t)(row0 + r) * EMB + cc);
        *reinterpret_cast<float4*>(&sA[r * SSTRIDE + cc]) = v;
    }
    if (tx < 64) {
        float2 bv = __ldg(reinterpret_cast<const float2*>(b) + tx);
        *reinterpret_cast<float2*>(&sB[tx * 2]) = bv;
    }
    __syncthreads();

    const int rowgrp = warpid >> 1;
    const int ch     = warpid & 1;
    const int g  = lane >> 2;
    const int tg = lane & 3;
    const int rloc0 = rowgrp * 16 + g;
    const int rloc1 = rloc0 + 8;

    float c[8][4];
#pragma unroll
    for (int j = 0; j < 8; j++)
#pragma unroll
        for (int q = 0; q < 4; q++) c[j][q] = 0.f;

#pragma unroll
    for (int kk = 0; kk < 8; kk++) {
        int kb = kk * 16;
        float2 f0 = *reinterpret_cast<const float2*>(&sA[rloc0 * SSTRIDE + kb + tg * 2]);
        float2 f1 = *reinterpret_cast<const float2*>(&sA[rloc1 * SSTRIDE + kb + tg * 2]);
        float2 f2 = *reinterpret_cast<const float2*>(&sA[rloc0 * SSTRIDE + kb + tg * 2 + 8]);
        float2 f3 = *reinterpret_cast<const float2*>(&sA[rloc1 * SSTRIDE + kb + tg * 2 + 8]);
        unsigned int a0 = h2u(__floats2half2_rn(f0.x, f0.y));
        unsigned int a1 = h2u(__floats2half2_rn(f1.x, f1.y));
        unsigned int a2 = h2u(__floats2half2_rn(f2.x, f2.y));
        unsigned int a3 = h2u(__floats2half2_rn(f3.x, f3.y));

        const uint4* wfk = wfrag + (size_t)kk * 256 + ch * 128 + lane;
#pragma unroll
        for (int jpl = 0; jpl < 4; jpl++) {
            uint4 bf = __ldg(wfk + jpl * 32);
            asm volatile(
                "mma.sync.aligned.m16n8k16.row.col.f32.f16.f16.f32 "
                "{%0,%1,%2,%3}, {%4,%5,%6,%7}, {%8,%9}, {%0,%1,%2,%3};"
                : "+f"(c[2*jpl][0]), "+f"(c[2*jpl][1]), "+f"(c[2*jpl][2]), "+f"(c[2*jpl][3])
                : "r"(a0), "r"(a1), "r"(a2), "r"(a3), "r"(bf.x), "r"(bf.y));
            asm volatile(
                "mma.sync.aligned.m16n8k16.row.col.f32.f16.f16.f32 "
                "{%0,%1,%2,%3}, {%4,%5,%6,%7}, {%8,%9}, {%0,%1,%2,%3};"
                : "+f"(c[2*jpl+1][0]), "+f"(c[2*jpl+1][1]), "+f"(c[2*jpl+1][2]), "+f"(c[2*jpl+1][3])
                : "r"(a0), "r"(a1), "r"(a2), "r"(a3), "r"(bf.z), "r"(bf.w));
        }
    }

#pragma unroll
    for (int j = 0; j < 8; j++) {
        int col = ch * 64 + j * 8 + tg * 2;
        float2 bb = *reinterpret_cast<const float2*>(&sB[col]);
        float2 e0 = *reinterpret_cast<float2*>(&sA[rloc0 * SSTRIDE + col]);
        float2 e1 = *reinterpret_cast<float2*>(&sA[rloc1 * SSTRIDE + col]);
        float2 o0, o1;
        o0.x = e0.x * sigmoid_t(c[j][0] + bb.x);
        o0.y = e0.y * sigmoid_t(c[j][1] + bb.y);
        o1.x = e1.x * sigmoid_t(c[j][2] + bb.x);
        o1.y = e1.y * sigmoid_t(c[j][3] + bb.y);
        *reinterpret_cast<float2*>(&sA[rloc0 * SSTRIDE + col]) = o0;
        *reinterpret_cast<float2*>(&sA[rloc1 * SSTRIDE + col]) = o1;
    }
    __syncthreads();

#pragma unroll
    for (int r = 0; r < 8; r++) {
        int grow = row0 + warpid * 8 + r;
        if (grow >= n) break;
        float4 o = *reinterpret_cast<float4*>(&sA[(warpid * 8 + r) * SSTRIDE + lane * 4]);
        *(reinterpret_cast<float4*>(acc + (size_t)grow * EMB) + lane) = o;
        __half2 h0 = __floats2half2_rn(o.x, o.y);
        __half2 h1 = __floats2half2_rn(o.z, o.w);
        uint2 hw;
        hw.x = h2u(h0);
        hw.y = h2u(h1);
        *(reinterpret_cast<uint2*>(u + (size_t)grow * EMB) + lane) = hw;
    }
}

// ---------------- fused SpMM + L2-normalize (deferred accumulate) -----------
// Warp per row; 16-edge batches with HFMA2 fp16 accumulation + fp32 flush.
__global__ void __launch_bounds__(256)
spmm_fused_kernel(const int* __restrict__ rs,
                  const int2* __restrict__ scv,
                  const __half* __restrict__ x,
                  __half* __restrict__ unext,
                  float* __restrict__ invout,
                  const float* __restrict__ invprev,
                  float* __restrict__ acc,
                  int n) {
    int row = (int)((blockIdx.x * (unsigned)blockDim.x + threadIdx.x) >> 5);
    int lane = threadIdx.x & 31;
    if (row >= n) return;

    const int ehalf = lane >> 4;
    const int fc    = lane & 15;

    int start = __ldg(rs + row);
    int deg   = __ldg(rs + row + 1) - start;

    float s[8];
#pragma unroll
    for (int i = 0; i < 8; i++) s[i] = 0.f;

    int j = 0;
    int2 cv[8];
    if (16 <= deg) {
#pragma unroll
        for (int i = 0; i < 8; i++)
            cv[i] = __ldg(scv + start + 2 * i + ehalf);
    }
    for (; j + 16 <= deg; j += 16) {
        uint4 xv[8];
#pragma unroll
        for (int i = 0; i < 8; i++)
            xv[i] = __ldg(reinterpret_cast<const uint4*>(x + cv[i].x) + fc);
        __half2 vh[8];
#pragma unroll
        for (int i = 0; i < 8; i++)
            vh[i] = __float2half2_rn(__int_as_float(cv[i].y));
        if (j + 32 <= deg) {   // prefetch next batch's edges under the math
#pragma unroll
            for (int i = 0; i < 8; i++)
                cv[i] = __ldg(scv + start + j + 16 + 2 * i + ehalf);
        }
        // fp16 accumulation within the batch (4 independent HFMA2 chains)
        __half2 a0 = __float2half2_rn(0.f), a1 = a0, a2 = a0, a3 = a0;
#pragma unroll
        for (int i = 0; i < 8; i++) {
            const __half2* hp = reinterpret_cast<const __half2*>(&xv[i]);
            a0 = __hfma2(hp[0], vh[i], a0);
            a1 = __hfma2(hp[1], vh[i], a1);
            a2 = __hfma2(hp[2], vh[i], a2);
            a3 = __hfma2(hp[3], vh[i], a3);
        }
        // flush batch partials to fp32
        float2 f0 = __half22float2(a0);
        float2 f1 = __half22float2(a1);
        float2 f2 = __half22float2(a2);
        float2 f3 = __half22float2(a3);
        s[0] += f0.x; s[1] += f0.y;
        s[2] += f1.x; s[3] += f1.y;
        s[4] += f2.x; s[5] += f2.y;
        s[6] += f3.x; s[7] += f3.y;
    }
    // 8-edge batch (fp32 exact)
    if (j + 8 <= deg) {
        int2 cvs[4];
#pragma unroll
        for (int i = 0; i < 4; i++)
            cvs[i] = __ldg(scv + start + j + 2 * i + ehalf);
        uint4 xv[4];
#pragma unroll
        for (int i = 0; i < 4; i++)
            xv[i] = __ldg(reinterpret_cast<const uint4*>(x + cvs[i].x) + fc);
#pragma unroll
        for (int i = 0; i < 4; i++) {
            float v = __int_as_float(cvs[i].y);
            const __half2* hp = reinterpret_cast<const __half2*>(&xv[i]);
            float2 f0 = __half22float2(hp[0]);
            float2 f1 = __half22float2(hp[1]);
            float2 f2 = __half22float2(hp[2]);
            float2 f3 = __half22float2(hp[3]);
            s[0] = fmaf(v, f0.x, s[0]); s[1] = fmaf(v, f0.y, s[1]);
            s[2] = fmaf(v, f1.x, s[2]); s[3] = fmaf(v, f1.y, s[3]);
            s[4] = fmaf(v, f2.x, s[4]); s[5] = fmaf(v, f2.y, s[5]);
            s[6] = fmaf(v, f3.x, s[6]); s[7] = fmaf(v, f3.y, s[7]);
        }
        j += 8;
    }
    // tail pairs (fp32 exact)
    for (; j < deg; j += 2) {
        int e = j + ehalf;
        int2 cvt = (e < deg) ? __ldg(scv + start + e) : make_int2(0, 0);
        float v = __int_as_float(cvt.y);
        uint4 xv = __ldg(reinterpret_cast<const uint4*>(x + cvt.x) + fc);
        const __half2* hp = reinterpret_cast<const __half2*>(&xv);
        float2 f0 = __half22float2(hp[0]);
        float2 f1 = __half22float2(hp[1]);
        float2 f2 = __half22float2(hp[2]);
        float2 f3 = __half22float2(hp[3]);
        s[0] = fmaf(v, f0.x, s[0]); s[1] = fmaf(v, f0.y, s[1]);
        s[2] = fmaf(v, f1.x, s[2]); s[3] = fmaf(v, f1.y, s[3]);
        s[4] = fmaf(v, f2.x, s[4]); s[5] = fmaf(v, f2.y, s[5]);
        s[6] = fmaf(v, f3.x, s[6]); s[7] = fmaf(v, f3.y, s[7]);
    }

#pragma unroll
    for (int i = 0; i < 8; i++)
        s[i] += __shfl_xor_sync(0xFFFFFFFFu, s[i], 16);

    float ss = s[0] * s[0] + s[1] * s[1] + s[2] * s[2] + s[3] * s[3]
             + s[4] * s[4] + s[5] * s[5] + s[6] * s[6] + s[7] * s[7];
#pragma unroll
    for (int o = 1; o < 16; o <<= 1) ss += __shfl_xor_sync(0xFFFFFFFFu, ss, o);
    float inv = 1.f / fmaxf(sqrtf(ss), 1e-12f);

    if (unext) {
        if (ehalf == 0) {
            __half2 h0 = __floats2half2_rn(s[0], s[1]);
            __half2 h1 = __floats2half2_rn(s[2], s[3]);
            __half2 h2 = __floats2half2_rn(s[4], s[5]);
            __half2 h3 = __floats2half2_rn(s[6], s[7]);
            uint4 hw;
            hw.x = h2u(h0); hw.y = h2u(h1);
            hw.z = h2u(h2); hw.w = h2u(h3);
            *(reinterpret_cast<uint4*>(unext + (size_t)row * EMB) + fc) = hw;
        }
        if (lane == 0) invout[row] = inv;
    } else {
        float ip = __ldg(invprev + row);
        int fbase = fc * 8 + ehalf * 4;
        const float* sp = s + ehalf * 4;
        uint2 raw = __ldg(reinterpret_cast<const uint2*>(x + (size_t)row * EMB + fbase));
        __half2 u1h0 = *reinterpret_cast<__half2*>(&raw.x);
        __half2 u1h1 = *reinterpret_cast<__half2*>(&raw.y);
        float2 u1f0 = __half22float2(u1h0);
        float2 u1f1 = __half22float2(u1h1);
        float4* ap = reinterpret_cast<float4*>(acc + (size_t)row * EMB + fbase);
        float4 a = *ap;
        a.x = fmaf(ip, u1f0.x, fmaf(sp[0], inv, a.x));
        a.y = fmaf(ip, u1f0.y, fmaf(sp[1], inv, a.y));
        a.z = fmaf(ip, u1f1.x, fmaf(sp[2], inv, a.z));
        a.w = fmaf(ip, u1f1.y, fmaf(sp[3], inv, a.w));
        *ap = a;
    }
}

// ---------------- launch -----------------------------------------------------
extern "C" void kernel_launch(void* const* d_in, const int* in_sizes, int n_in,
                              void* d_out, int out_size) {
    const float* emb  = (const float*)d_in[0];
    const float* W    = (const float*)d_in[1];
    const float* bias = (const float*)d_in[2];
    const int*   rows = (const int*)  d_in[3];
    const int*   cols = (const int*)  d_in[4];
    const float* vals = (const float*)d_in[5];

    int n   = in_sizes[0] / EMB;
    int nnz = in_sizes[3];
    float* acc = (float*)d_out;

    __half *bufA, *bufB;
    int *csrws, *rs, *cur;
    int2 *scv;
    uint4 *wfrag;
    float *invb;
    cudaGetSymbolAddress((void**)&bufA,  g_bufA);
    cudaGetSymbolAddress((void**)&bufB,  g_bufB);
    cudaGetSymbolAddress((void**)&csrws, g_csrws);
    cudaGetSymbolAddress((void**)&rs,    g_rs);
    cudaGetSymbolAddress((void**)&cur,   g_cur);
    cudaGetSymbolAddress((void**)&scv,   g_scv);
    cudaGetSymbolAddress((void**)&wfrag, g_wfrag);
    cudaGetSymbolAddress((void**)&invb,  g_inv);

    int* cnt = csrws;
    unsigned long long* stat = (unsigned long long*)(csrws + n);
    int* ticket = csrws + n + 52;
    int* done   = csrws + n + 53;

    // K1: hist + W-fragment transpose
    hist_wtrans_kernel<<<8 + (nnz + 255) / 256, 256>>>(rows, cnt, nnz, W, wfrag);

    // K2: scan (self-cleaning)
    int nb = (n + 4095) / 4096;
    scan_kernel<<<nb, 1024>>>(cnt, rs, cur, stat, ticket, done, n);

    // K3: scatter
    scatter_kernel<<<(nnz + 255) / 256, 256>>>(rows, cols, vals, cur, scv, nnz);

    // K4: gate (u0 -> bufA fp16, acc = u0 fp32)
    int smem_bytes = 64 * SSTRIDE * sizeof(float);
    cudaFuncSetAttribute(gate_mma_kernel,
                         cudaFuncAttributeMaxDynamicSharedMemorySize, smem_bytes);
    gate_mma_kernel<<<(n + 63) / 64, 256, smem_bytes>>>(emb, wfrag, bias, bufA, acc, n);

    // K5/K6: fused spmm layers
    unsigned spmm_blocks = (unsigned)(((size_t)n * 32 + 255) / 256);
    spmm_fused_kernel<<<spmm_blocks, 256>>>(rs, scv, bufA, bufB, invb, nullptr, nullptr, n);
    spmm_fused_kernel<<<spmm_blocks, 256>>>(rs, scv, bufB, nullptr, nullptr, invb, acc, n);
}

// round 13
// speedup vs baseline: 1.0047x; 1.0047x over previous
#include <cuda_runtime.h>
#include <cuda_fp16.h>
#include <cstdint>

#define EMB 128
#define MAX_NODES 100000
#define MAX_EDGES 1600000
#define SSTRIDE 132   // padded smem row stride (floats): conflict-free frag reads

// ---------------- scratch (static device globals: allocation-guard safe) ----
__device__ __half g_bufA[(size_t)MAX_NODES * EMB];
__device__ __half g_bufB[(size_t)MAX_NODES * EMB];
__device__ int    g_csrws[MAX_NODES + 64];   // cnt | stat(52) | ticket | done
__device__ int    g_rs[MAX_NODES + 1];
__device__ int    g_cur[MAX_NODES];
__device__ float  g_inv[MAX_NODES];
__device__ int2   g_scv[MAX_EDGES];          // (col<<7 element offset, val bits)
__device__ uint4  g_wfrag[8 * 8 * 32];       // fp16 B-fragments, j-pair packed (32 KB)

__device__ __forceinline__ float sigmoid_t(float z) {
    float t;
    asm("tanh.approx.f32 %0, %1;" : "=f"(t) : "f"(0.5f * z));
    return fmaf(0.5f, t, 0.5f);
}

__device__ __forceinline__ unsigned int h2u(__half2 h) {
    return *reinterpret_cast<unsigned int*>(&h);
}

// ---------------- hist + W-fragment transpose (fused) ------------------------
__global__ void hist_wtrans_kernel(const int* __restrict__ rows,
                                   int* __restrict__ cnt, int nnz,
                                   const float* __restrict__ W,
                                   uint4* __restrict__ wfrag) {
    if (blockIdx.x < 8) {
        int id = blockIdx.x * 256 + threadIdx.x;    // 0..2047
        int lane = id & 31;
        int jp = (id >> 5) & 7;
        int kk = id >> 8;
        int g  = lane >> 2;
        int tg = lane & 3;
        int k0 = kk * 16 + tg * 2;
        int col0 = (2 * jp)     * 8 + g;
        int col1 = (2 * jp + 1) * 8 + g;
        __half2 b0j0 = __floats2half2_rn(W[(size_t)k0       * EMB + col0], W[(size_t)(k0 + 1) * EMB + col0]);
        __half2 b1j0 = __floats2half2_rn(W[(size_t)(k0 + 8) * EMB + col0], W[(size_t)(k0 + 9) * EMB + col0]);
        __half2 b0j1 = __floats2half2_rn(W[(size_t)k0       * EMB + col1], W[(size_t)(k0 + 1) * EMB + col1]);
        __half2 b1j1 = __floats2half2_rn(W[(size_t)(k0 + 8) * EMB + col1], W[(size_t)(k0 + 9) * EMB + col1]);
        uint4 v;
        v.x = h2u(b0j0); v.y = h2u(b1j0);
        v.z = h2u(b0j1); v.w = h2u(b1j1);
        wfrag[id] = v;
    } else {
        int e = (blockIdx.x - 8) * 256 + threadIdx.x;
        if (e < nnz) atomicAdd(&cnt[rows[e]], 1);
    }
}

// ---------------- single-pass decoupled-lookback scan (self-cleaning) --------
__global__ void scan_kernel(int* __restrict__ cnt,
                            int* __restrict__ rs, int* __restrict__ cur,
                            unsigned long long* __restrict__ stat,
                            int* __restrict__ ticket, int* __restrict__ done,
                            int n) {
    __shared__ int sbid;
    __shared__ int warpsum[32];
    __shared__ int sprefix;
    int t = threadIdx.x;
    if (t == 0) sbid = atomicAdd(ticket, 1);
    __syncthreads();
    int bid = sbid;

    int base = bid * 4096 + t * 4;
    int4 c = make_int4(0, 0, 0, 0);
    if (base + 3 < n) {
        c = *reinterpret_cast<const int4*>(cnt + base);
        *reinterpret_cast<int4*>(cnt + base) = make_int4(0, 0, 0, 0);
    } else {
        if (base     < n) { c.x = cnt[base];     cnt[base]     = 0; }
        if (base + 1 < n) { c.y = cnt[base + 1]; cnt[base + 1] = 0; }
        if (base + 2 < n) { c.z = cnt[base + 2]; cnt[base + 2] = 0; }
        if (base + 3 < n) { c.w = cnt[base + 3]; cnt[base + 3] = 0; }
    }
    int tot = c.x + c.y + c.z + c.w;
    int lane = t & 31, wid = t >> 5;
    int inc = tot;
#pragma unroll
    for (int o = 1; o < 32; o <<= 1) {
        int u = __shfl_up_sync(0xFFFFFFFFu, inc, o);
        if (lane >= o) inc += u;
    }
    if (lane == 31) warpsum[wid] = inc;
    __syncthreads();
    if (wid == 0) {
        int w = warpsum[lane];
#pragma unroll
        for (int o = 1; o < 32; o <<= 1) {
            int u = __shfl_up_sync(0xFFFFFFFFu, w, o);
            if (lane >= o) w += u;
        }
        warpsum[lane] = w;
    }
    __syncthreads();
    int blocktot = warpsum[31];
    int excl = inc - tot + (wid ? warpsum[wid - 1] : 0);

    if (t == 0) {
        if (bid == 0) {
            atomicExch(&stat[0], (2ull << 32) | (unsigned)blocktot);
            sprefix = 0;
        } else {
            atomicExch(&stat[bid], (1ull << 32) | (unsigned)blocktot);
            int pre = 0;
            for (int i = bid - 1; i >= 0; i--) {
                unsigned long long s;
                do { s = atomicAdd(&stat[i], 0ull); } while ((s >> 32) == 0ull);
                pre += (int)(unsigned)s;
                if ((s >> 32) == 2ull) break;
            }
            atomicExch(&stat[bid], (2ull << 32) | (unsigned)(pre + blocktot));
            sprefix = pre;
        }
    }
    __syncthreads();
    int prefix = sprefix;

    int v0 = excl + prefix;
    if (base     < n) { rs[base]     = v0;                   cur[base]     = v0; }
    if (base + 1 < n) { rs[base + 1] = v0 + c.x;             cur[base + 1] = v0 + c.x; }
    if (base + 2 < n) { rs[base + 2] = v0 + c.x + c.y;       cur[base + 2] = v0 + c.x + c.y; }
    if (base + 3 < n) { rs[base + 3] = v0 + c.x + c.y + c.z; cur[base + 3] = v0 + c.x + c.y + c.z; }
    if (bid == gridDim.x - 1 && t == 1023) rs[n] = prefix + blocktot;

    __syncthreads();
    if (t == 0) {
        int d = atomicAdd(done, 1);
        if (d == (int)gridDim.x - 1) {
            for (int i = 0; i < (int)gridDim.x; i++) stat[i] = 0ull;
            *ticket = 0;
            *done = 0;
        }
    }
}

__global__ void scatter_kernel(const int* __restrict__ rows,
                               const int* __restrict__ cols,
                               const float* __restrict__ vals,
                               int* __restrict__ cur,
                               int2* __restrict__ scv, int nnz) {
    int e = blockIdx.x * 256 + threadIdx.x;
    if (e >= nnz) return;
    int p = atomicAdd(&cur[rows[e]], 1);
    scv[p] = make_int2(cols[e] << 7, __float_as_int(vals[e]));   // element offset
}

// ---------------- self-gating: fp16 warp-MMA, 64-row tiles ------------------
// __launch_bounds__(256, 4): cap regs at 64 -> 4 resident blocks (32 warps/SM)
__global__ void __launch_bounds__(256, 4)
gate_mma_kernel(const float* __restrict__ emb,
                const uint4* __restrict__ wfrag,
                const float* __restrict__ b,
                __half* __restrict__ u,
                float* __restrict__ acc,
                int n) {
    extern __shared__ float sA[];              // [64][SSTRIDE]
    __shared__ float sB[EMB];
    const int tx = threadIdx.x;
    const int warpid = tx >> 5;
    const int lane = tx & 31;
    const int row0 = blockIdx.x * 64;

    for (int i = tx; i < 64 * 32; i += 256) {
        int r = i >> 5;
        int cc = (i & 31) * 4;
        float4 v = make_float4(0.f, 0.f, 0.f, 0.f);
        if (row0 + r < n)
            v = *reinterpret_cast<const float4*>(emb + (size_t)(row0 + r) * EMB + cc);
        *reinterpret_cast<float4*>(&sA[r * SSTRIDE + cc]) = v;
    }
    if (tx < 64) {
        float2 bv = __ldg(reinterpret_cast<const float2*>(b) + tx);
        *reinterpret_cast<float2*>(&sB[tx * 2]) = bv;
    }
    __syncthreads();

    const int rowgrp = warpid >> 1;
    const int ch     = warpid & 1;
    const int g  = lane >> 2;
    const int tg = lane & 3;
    const int rloc0 = rowgrp * 16 + g;
    const int rloc1 = rloc0 + 8;

    float c[8][4];
#pragma unroll
    for (int j = 0; j < 8; j++)
#pragma unroll
        for (int q = 0; q < 4; q++) c[j][q] = 0.f;

#pragma unroll
    for (int kk = 0; kk < 8; kk++) {
        int kb = kk * 16;
        float2 f0 = *reinterpret_cast<const float2*>(&sA[rloc0 * SSTRIDE + kb + tg * 2]);
        float2 f1 = *reinterpret_cast<const float2*>(&sA[rloc1 * SSTRIDE + kb + tg * 2]);
        float2 f2 = *reinterpret_cast<const float2*>(&sA[rloc0 * SSTRIDE + kb + tg * 2 + 8]);
        float2 f3 = *reinterpret_cast<const float2*>(&sA[rloc1 * SSTRIDE + kb + tg * 2 + 8]);
        unsigned int a0 = h2u(__floats2half2_rn(f0.x, f0.y));
        unsigned int a1 = h2u(__floats2half2_rn(f1.x, f1.y));
        unsigned int a2 = h2u(__floats2half2_rn(f2.x, f2.y));
        unsigned int a3 = h2u(__floats2half2_rn(f3.x, f3.y));

        const uint4* wfk = wfrag + (size_t)kk * 256 + ch * 128 + lane;
#pragma unroll
        for (int jpl = 0; jpl < 4; jpl++) {
            uint4 bf = __ldg(wfk + jpl * 32);
            asm volatile(
                "mma.sync.aligned.m16n8k16.row.col.f32.f16.f16.f32 "
                "{%0,%1,%2,%3}, {%4,%5,%6,%7}, {%8,%9}, {%0,%1,%2,%3};"
                : "+f"(c[2*jpl][0]), "+f"(c[2*jpl][1]), "+f"(c[2*jpl][2]), "+f"(c[2*jpl][3])
                : "r"(a0), "r"(a1), "r"(a2), "r"(a3), "r"(bf.x), "r"(bf.y));
            asm volatile(
                "mma.sync.aligned.m16n8k16.row.col.f32.f16.f16.f32 "
                "{%0,%1,%2,%3}, {%4,%5,%6,%7}, {%8,%9}, {%0,%1,%2,%3};"
                : "+f"(c[2*jpl+1][0]), "+f"(c[2*jpl+1][1]), "+f"(c[2*jpl+1][2]), "+f"(c[2*jpl+1][3])
                : "r"(a0), "r"(a1), "r"(a2), "r"(a3), "r"(bf.z), "r"(bf.w));
        }
    }

#pragma unroll
    for (int j = 0; j < 8; j++) {
        int col = ch * 64 + j * 8 + tg * 2;
        float2 bb = *reinterpret_cast<const float2*>(&sB[col]);
        float2 e0 = *reinterpret_cast<float2*>(&sA[rloc0 * SSTRIDE + col]);
        float2 e1 = *reinterpret_cast<float2*>(&sA[rloc1 * SSTRIDE + col]);
        float2 o0, o1;
        o0.x = e0.x * sigmoid_t(c[j][0] + bb.x);
        o0.y = e0.y * sigmoid_t(c[j][1] + bb.y);
        o1.x = e1.x * sigmoid_t(c[j][2] + bb.x);
        o1.y = e1.y * sigmoid_t(c[j][3] + bb.y);
        *reinterpret_cast<float2*>(&sA[rloc0 * SSTRIDE + col]) = o0;
        *reinterpret_cast<float2*>(&sA[rloc1 * SSTRIDE + col]) = o1;
    }
    __syncthreads();

#pragma unroll
    for (int r = 0; r < 8; r++) {
        int grow = row0 + warpid * 8 + r;
        if (grow >= n) break;
        float4 o = *reinterpret_cast<float4*>(&sA[(warpid * 8 + r) * SSTRIDE + lane * 4]);
        *(reinterpret_cast<float4*>(acc + (size_t)grow * EMB) + lane) = o;
        __half2 h0 = __floats2half2_rn(o.x, o.y);
        __half2 h1 = __floats2half2_rn(o.z, o.w);
        uint2 hw;
        hw.x = h2u(h0);
        hw.y = h2u(h1);
        *(reinterpret_cast<uint2*>(u + (size_t)grow * EMB) + lane) = hw;
    }
}

// ---------------- fused SpMM + L2-normalize (deferred accumulate) -----------
// Warp per row; fp32 FFMA inner loop (proven fastest), 16-edge batches + prefetch.
__global__ void __launch_bounds__(256)
spmm_fused_kernel(const int* __restrict__ rs,
                  const int2* __restrict__ scv,
                  const __half* __restrict__ x,
                  __half* __restrict__ unext,
                  float* __restrict__ invout,
                  const float* __restrict__ invprev,
                  float* __restrict__ acc,
                  int n) {
    int row = (int)((blockIdx.x * (unsigned)blockDim.x + threadIdx.x) >> 5);
    int lane = threadIdx.x & 31;
    if (row >= n) return;

    const int ehalf = lane >> 4;
    const int fc    = lane & 15;

    int start = __ldg(rs + row);
    int deg   = __ldg(rs + row + 1) - start;

    float s[8];
#pragma unroll
    for (int i = 0; i < 8; i++) s[i] = 0.f;

    int j = 0;
    int2 cv[8];
    if (16 <= deg) {
#pragma unroll
        for (int i = 0; i < 8; i++)
            cv[i] = __ldg(scv + start + 2 * i + ehalf);
    }
    for (; j + 16 <= deg; j += 16) {
        uint4 xv[8];
#pragma unroll
        for (int i = 0; i < 8; i++)
            xv[i] = __ldg(reinterpret_cast<const uint4*>(x + cv[i].x) + fc);
        float vv[8];
#pragma unroll
        for (int i = 0; i < 8; i++) vv[i] = __int_as_float(cv[i].y);
        if (j + 32 <= deg) {   // prefetch next batch's edges under the math
#pragma unroll
            for (int i = 0; i < 8; i++)
                cv[i] = __ldg(scv + start + j + 16 + 2 * i + ehalf);
        }
#pragma unroll
        for (int i = 0; i < 8; i++) {
            float v = vv[i];
            const __half2* hp = reinterpret_cast<const __half2*>(&xv[i]);
            float2 f0 = __half22float2(hp[0]);
            float2 f1 = __half22float2(hp[1]);
            float2 f2 = __half22float2(hp[2]);
            float2 f3 = __half22float2(hp[3]);
            s[0] = fmaf(v, f0.x, s[0]); s[1] = fmaf(v, f0.y, s[1]);
            s[2] = fmaf(v, f1.x, s[2]); s[3] = fmaf(v, f1.y, s[3]);
            s[4] = fmaf(v, f2.x, s[4]); s[5] = fmaf(v, f2.y, s[5]);
            s[6] = fmaf(v, f3.x, s[6]); s[7] = fmaf(v, f3.y, s[7]);
        }
    }
    if (j + 8 <= deg) {
        int2 cvs[4];
#pragma unroll
        for (int i = 0; i < 4; i++)
            cvs[i] = __ldg(scv + start + j + 2 * i + ehalf);
        uint4 xv[4];
#pragma unroll
        for (int i = 0; i < 4; i++)
            xv[i] = __ldg(reinterpret_cast<const uint4*>(x + cvs[i].x) + fc);
#pragma unroll
        for (int i = 0; i < 4; i++) {
            float v = __int_as_float(cvs[i].y);
            const __half2* hp = reinterpret_cast<const __half2*>(&xv[i]);
            float2 f0 = __half22float2(hp[0]);
            float2 f1 = __half22float2(hp[1]);
            float2 f2 = __half22float2(hp[2]);
            float2 f3 = __half22float2(hp[3]);
            s[0] = fmaf(v, f0.x, s[0]); s[1] = fmaf(v, f0.y, s[1]);
            s[2] = fmaf(v, f1.x, s[2]); s[3] = fmaf(v, f1.y, s[3]);
            s[4] = fmaf(v, f2.x, s[4]); s[5] = fmaf(v, f2.y, s[5]);
            s[6] = fmaf(v, f3.x, s[6]); s[7] = fmaf(v, f3.y, s[7]);
        }
        j += 8;
    }
    for (; j < deg; j += 2) {
        int e = j + ehalf;
        int2 cvt = (e < deg) ? __ldg(scv + start + e) : make_int2(0, 0);
        float v = __int_as_float(cvt.y);
        uint4 xv = __ldg(reinterpret_cast<const uint4*>(x + cvt.x) + fc);
        const __half2* hp = reinterpret_cast<const __half2*>(&xv);
        float2 f0 = __half22float2(hp[0]);
        float2 f1 = __half22float2(hp[1]);
        float2 f2 = __half22float2(hp[2]);
        float2 f3 = __half22float2(hp[3]);
        s[0] = fmaf(v, f0.x, s[0]); s[1] = fmaf(v, f0.y, s[1]);
        s[2] = fmaf(v, f1.x, s[2]); s[3] = fmaf(v, f1.y, s[3]);
        s[4] = fmaf(v, f2.x, s[4]); s[5] = fmaf(v, f2.y, s[5]);
        s[6] = fmaf(v, f3.x, s[6]); s[7] = fmaf(v, f3.y, s[7]);
    }

#pragma unroll
    for (int i = 0; i < 8; i++)
        s[i] += __shfl_xor_sync(0xFFFFFFFFu, s[i], 16);

    float ss = s[0] * s[0] + s[1] * s[1] + s[2] * s[2] + s[3] * s[3]
             + s[4] * s[4] + s[5] * s[5] + s[6] * s[6] + s[7] * s[7];
#pragma unroll
    for (int o = 1; o < 16; o <<= 1) ss += __shfl_xor_sync(0xFFFFFFFFu, ss, o);
    float inv = 1.f / fmaxf(sqrtf(ss), 1e-12f);

    if (unext) {
        if (ehalf == 0) {
            __half2 h0 = __floats2half2_rn(s[0], s[1]);
            __half2 h1 = __floats2half2_rn(s[2], s[3]);
            __half2 h2 = __floats2half2_rn(s[4], s[5]);
            __half2 h3 = __floats2half2_rn(s[6], s[7]);
            uint4 hw;
            hw.x = h2u(h0); hw.y = h2u(h1);
            hw.z = h2u(h2); hw.w = h2u(h3);
            *(reinterpret_cast<uint4*>(unext + (size_t)row * EMB) + fc) = hw;
        }
        if (lane == 0) invout[row] = inv;
    } else {
        float ip = __ldg(invprev + row);
        int fbase = fc * 8 + ehalf * 4;
        const float* sp = s + ehalf * 4;
        uint2 raw = __ldg(reinterpret_cast<const uint2*>(x + (size_t)row * EMB + fbase));
        __half2 u1h0 = *reinterpret_cast<__half2*>(&raw.x);
        __half2 u1h1 = *reinterpret_cast<__half2*>(&raw.y);
        float2 u1f0 = __half22float2(u1h0);
        float2 u1f1 = __half22float2(u1h1);
        float4* ap = reinterpret_cast<float4*>(acc + (size_t)row * EMB + fbase);
        float4 a = *ap;
        a.x = fmaf(ip, u1f0.x, fmaf(sp[0], inv, a.x));
        a.y = fmaf(ip, u1f0.y, fmaf(sp[1], inv, a.y));
        a.z = fmaf(ip, u1f1.x, fmaf(sp[2], inv, a.z));
        a.w = fmaf(ip, u1f1.y, fmaf(sp[3], inv, a.w));
        *ap = a;
    }
}

// ---------------- launch -----------------------------------------------------
extern "C" void kernel_launch(void* const* d_in, const int* in_sizes, int n_in,
                              void* d_out, int out_size) {
    const float* emb  = (const float*)d_in[0];
    const float* W    = (const float*)d_in[1];
    const float* bias = (const float*)d_in[2];
    const int*   rows = (const int*)  d_in[3];
    const int*   cols = (const int*)  d_in[4];
    const float* vals = (const float*)d_in[5];

    int n   = in_sizes[0] / EMB;
    int nnz = in_sizes[3];
    float* acc = (float*)d_out;

    __half *bufA, *bufB;
    int *csrws, *rs, *cur;
    int2 *scv;
    uint4 *wfrag;
    float *invb;
    cudaGetSymbolAddress((void**)&bufA,  g_bufA);
    cudaGetSymbolAddress((void**)&bufB,  g_bufB);
    cudaGetSymbolAddress((void**)&csrws, g_csrws);
    cudaGetSymbolAddress((void**)&rs,    g_rs);
    cudaGetSymbolAddress((void**)&cur,   g_cur);
    cudaGetSymbolAddress((void**)&scv,   g_scv);
    cudaGetSymbolAddress((void**)&wfrag, g_wfrag);
    cudaGetSymbolAddress((void**)&invb,  g_inv);

    int* cnt = csrws;
    unsigned long long* stat = (unsigned long long*)(csrws + n);
    int* ticket = csrws + n + 52;
    int* done   = csrws + n + 53;

    // K1: hist + W-fragment transpose
    hist_wtrans_kernel<<<8 + (nnz + 255) / 256, 256>>>(rows, cnt, nnz, W, wfrag);

    // K2: scan (self-cleaning)
    int nb = (n + 4095) / 4096;
    scan_kernel<<<nb, 1024>>>(cnt, rs, cur, stat, ticket, done, n);

    // K3: scatter
    scatter_kernel<<<(nnz + 255) / 256, 256>>>(rows, cols, vals, cur, scv, nnz);

    // K4: gate (u0 -> bufA fp16, acc = u0 fp32)
    int smem_bytes = 64 * SSTRIDE * sizeof(float);
    cudaFuncSetAttribute(gate_mma_kernel,
                         cudaFuncAttributeMaxDynamicSharedMemorySize, smem_bytes);
    gate_mma_kernel<<<(n + 63) / 64, 256, smem_bytes>>>(emb, wfrag, bias, bufA, acc, n);

    // K5/K6: fused spmm layers
    unsigned spmm_blocks = (unsigned)(((size_t)n * 32 + 255) / 256);
    spmm_fused_kernel<<<spmm_blocks, 256>>>(rs, scv, bufA, bufB, invb, nullptr, nullptr, n);
    spmm_fused_kernel<<<spmm_blocks, 256>>>(rs, scv, bufB, nullptr, nullptr, invb, acc, n);
}

// round 14
// speedup vs baseline: 1.0850x; 1.0799x over previous
#include <cuda_runtime.h>
#include <cuda_fp16.h>
#include <cstdint>

#define EMB 128
#define MAX_NODES 100000
#define MAX_EDGES 1600000
#define SSTRIDE 132   // padded smem row stride (floats): conflict-free frag reads

// ---------------- scratch (static device globals: allocation-guard safe) ----
__device__ __half g_bufA[(size_t)MAX_NODES * EMB];
__device__ __half g_bufB[(size_t)MAX_NODES * EMB];
__device__ int    g_csrws[MAX_NODES + 64];   // cnt | stat(52) | ticket | done
__device__ int    g_rs[MAX_NODES + 1];
__device__ int    g_cur[MAX_NODES];
__device__ float  g_inv[MAX_NODES];
__device__ int2   g_scv[MAX_EDGES];          // (col, val bits)
__device__ uint4  g_wfrag[8 * 8 * 32];       // fp16 B-fragments, j-pair packed (32 KB)

__device__ __forceinline__ float sigmoid_t(float z) {
    float t;
    asm("tanh.approx.f32 %0, %1;" : "=f"(t) : "f"(0.5f * z));
    return fmaf(0.5f, t, 0.5f);
}

__device__ __forceinline__ unsigned int h2u(__half2 h) {
    return *reinterpret_cast<unsigned int*>(&h);
}

// ---------------- hist + W-fragment transpose (fused) ------------------------
__global__ void hist_wtrans_kernel(const int* __restrict__ rows,
                                   int* __restrict__ cnt, int nnz,
                                   const float* __restrict__ W,
                                   uint4* __restrict__ wfrag) {
    if (blockIdx.x < 8) {
        int id = blockIdx.x * 256 + threadIdx.x;    // 0..2047
        int lane = id & 31;
        int jp = (id >> 5) & 7;
        int kk = id >> 8;
        int g  = lane >> 2;
        int tg = lane & 3;
        int k0 = kk * 16 + tg * 2;
        int col0 = (2 * jp)     * 8 + g;
        int col1 = (2 * jp + 1) * 8 + g;
        __half2 b0j0 = __floats2half2_rn(W[(size_t)k0       * EMB + col0], W[(size_t)(k0 + 1) * EMB + col0]);
        __half2 b1j0 = __floats2half2_rn(W[(size_t)(k0 + 8) * EMB + col0], W[(size_t)(k0 + 9) * EMB + col0]);
        __half2 b0j1 = __floats2half2_rn(W[(size_t)k0       * EMB + col1], W[(size_t)(k0 + 1) * EMB + col1]);
        __half2 b1j1 = __floats2half2_rn(W[(size_t)(k0 + 8) * EMB + col1], W[(size_t)(k0 + 9) * EMB + col1]);
        uint4 v;
        v.x = h2u(b0j0); v.y = h2u(b1j0);
        v.z = h2u(b0j1); v.w = h2u(b1j1);
        wfrag[id] = v;
    } else {
        int e = (blockIdx.x - 8) * 256 + threadIdx.x;
        if (e < nnz) atomicAdd(&cnt[rows[e]], 1);
    }
}

// ---------------- single-pass decoupled-lookback scan (self-cleaning) --------
__global__ void scan_kernel(int* __restrict__ cnt,
                            int* __restrict__ rs, int* __restrict__ cur,
                            unsigned long long* __restrict__ stat,
                            int* __restrict__ ticket, int* __restrict__ done,
                            int n) {
    __shared__ int sbid;
    __shared__ int warpsum[32];
    __shared__ int sprefix;
    int t = threadIdx.x;
    if (t == 0) sbid = atomicAdd(ticket, 1);
    __syncthreads();
    int bid = sbid;

    int base = bid * 4096 + t * 4;
    int4 c = make_int4(0, 0, 0, 0);
    if (base + 3 < n) {
        c = *reinterpret_cast<const int4*>(cnt + base);
        *reinterpret_cast<int4*>(cnt + base) = make_int4(0, 0, 0, 0);
    } else {
        if (base     < n) { c.x = cnt[base];     cnt[base]     = 0; }
        if (base + 1 < n) { c.y = cnt[base + 1]; cnt[base + 1] = 0; }
        if (base + 2 < n) { c.z = cnt[base + 2]; cnt[base + 2] = 0; }
        if (base + 3 < n) { c.w = cnt[base + 3]; cnt[base + 3] = 0; }
    }
    int tot = c.x + c.y + c.z + c.w;
    int lane = t & 31, wid = t >> 5;
    int inc = tot;
#pragma unroll
    for (int o = 1; o < 32; o <<= 1) {
        int u = __shfl_up_sync(0xFFFFFFFFu, inc, o);
        if (lane >= o) inc += u;
    }
    if (lane == 31) warpsum[wid] = inc;
    __syncthreads();
    if (wid == 0) {
        int w = warpsum[lane];
#pragma unroll
        for (int o = 1; o < 32; o <<= 1) {
            int u = __shfl_up_sync(0xFFFFFFFFu, w, o);
            if (lane >= o) w += u;
        }
        warpsum[lane] = w;
    }
    __syncthreads();
    int blocktot = warpsum[31];
    int excl = inc - tot + (wid ? warpsum[wid - 1] : 0);

    if (t == 0) {
        if (bid == 0) {
            atomicExch(&stat[0], (2ull << 32) | (unsigned)blocktot);
            sprefix = 0;
        } else {
            atomicExch(&stat[bid], (1ull << 32) | (unsigned)blocktot);
            int pre = 0;
            for (int i = bid - 1; i >= 0; i--) {
                unsigned long long s;
                do { s = atomicAdd(&stat[i], 0ull); } while ((s >> 32) == 0ull);
                pre += (int)(unsigned)s;
                if ((s >> 32) == 2ull) break;
            }
            atomicExch(&stat[bid], (2ull << 32) | (unsigned)(pre + blocktot));
            sprefix = pre;
        }
    }
    __syncthreads();
    int prefix = sprefix;

    int v0 = excl + prefix;
    if (base     < n) { rs[base]     = v0;                   cur[base]     = v0; }
    if (base + 1 < n) { rs[base + 1] = v0 + c.x;             cur[base + 1] = v0 + c.x; }
    if (base + 2 < n) { rs[base + 2] = v0 + c.x + c.y;       cur[base + 2] = v0 + c.x + c.y; }
    if (base + 3 < n) { rs[base + 3] = v0 + c.x + c.y + c.z; cur[base + 3] = v0 + c.x + c.y + c.z; }
    if (bid == gridDim.x - 1 && t == 1023) rs[n] = prefix + blocktot;

    __syncthreads();
    if (t == 0) {
        int d = atomicAdd(done, 1);
        if (d == (int)gridDim.x - 1) {
            for (int i = 0; i < (int)gridDim.x; i++) stat[i] = 0ull;
            *ticket = 0;
            *done = 0;
        }
    }
}

__global__ void scatter_kernel(const int* __restrict__ rows,
                               const int* __restrict__ cols,
                               const float* __restrict__ vals,
                               int* __restrict__ cur,
                               int2* __restrict__ scv, int nnz) {
    int e = blockIdx.x * 256 + threadIdx.x;
    if (e >= nnz) return;
    int p = atomicAdd(&cur[rows[e]], 1);
    scv[p] = make_int2(cols[e], __float_as_int(vals[e]));
}

// ---------------- self-gating: fp16 warp-MMA, 64-row tiles ------------------
// __launch_bounds__(256, 4): 64 regs -> 4 resident blocks (measured 39.7us)
__global__ void __launch_bounds__(256, 4)
gate_mma_kernel(const float* __restrict__ emb,
                const uint4* __restrict__ wfrag,
                const float* __restrict__ b,
                __half* __restrict__ u,
                float* __restrict__ acc,
                int n) {
    extern __shared__ float sA[];              // [64][SSTRIDE]
    __shared__ float sB[EMB];
    const int tx = threadIdx.x;
    const int warpid = tx >> 5;
    const int lane = tx & 31;
    const int row0 = blockIdx.x * 64;

    for (int i = tx; i < 64 * 32; i += 256) {
        int r = i >> 5;
        int cc = (i & 31) * 4;
        float4 v = make_float4(0.f, 0.f, 0.f, 0.f);
        if (row0 + r < n)
            v = *reinterpret_cast<const float4*>(emb + (size_t)(row0 + r) * EMB + cc);
        *reinterpret_cast<float4*>(&sA[r * SSTRIDE + cc]) = v;
    }
    if (tx < 64) {
        float2 bv = __ldg(reinterpret_cast<const float2*>(b) + tx);
        *reinterpret_cast<float2*>(&sB[tx * 2]) = bv;
    }
    __syncthreads();

    const int rowgrp = warpid >> 1;
    const int ch     = warpid & 1;
    const int g  = lane >> 2;
    const int tg = lane & 3;
    const int rloc0 = rowgrp * 16 + g;
    const int rloc1 = rloc0 + 8;

    float c[8][4];
#pragma unroll
    for (int j = 0; j < 8; j++)
#pragma unroll
        for (int q = 0; q < 4; q++) c[j][q] = 0.f;

#pragma unroll
    for (int kk = 0; kk < 8; kk++) {
        int kb = kk * 16;
        float2 f0 = *reinterpret_cast<const float2*>(&sA[rloc0 * SSTRIDE + kb + tg * 2]);
        float2 f1 = *reinterpret_cast<const float2*>(&sA[rloc1 * SSTRIDE + kb + tg * 2]);
        float2 f2 = *reinterpret_cast<const float2*>(&sA[rloc0 * SSTRIDE + kb + tg * 2 + 8]);
        float2 f3 = *reinterpret_cast<const float2*>(&sA[rloc1 * SSTRIDE + kb + tg * 2 + 8]);
        unsigned int a0 = h2u(__floats2half2_rn(f0.x, f0.y));
        unsigned int a1 = h2u(__floats2half2_rn(f1.x, f1.y));
        unsigned int a2 = h2u(__floats2half2_rn(f2.x, f2.y));
        unsigned int a3 = h2u(__floats2half2_rn(f3.x, f3.y));

        const uint4* wfk = wfrag + (size_t)kk * 256 + ch * 128 + lane;
#pragma unroll
        for (int jpl = 0; jpl < 4; jpl++) {
            uint4 bf = __ldg(wfk + jpl * 32);
            asm volatile(
                "mma.sync.aligned.m16n8k16.row.col.f32.f16.f16.f32 "
                "{%0,%1,%2,%3}, {%4,%5,%6,%7}, {%8,%9}, {%0,%1,%2,%3};"
                : "+f"(c[2*jpl][0]), "+f"(c[2*jpl][1]), "+f"(c[2*jpl][2]), "+f"(c[2*jpl][3])
                : "r"(a0), "r"(a1), "r"(a2), "r"(a3), "r"(bf.x), "r"(bf.y));
            asm volatile(
                "mma.sync.aligned.m16n8k16.row.col.f32.f16.f16.f32 "
                "{%0,%1,%2,%3}, {%4,%5,%6,%7}, {%8,%9}, {%0,%1,%2,%3};"
                : "+f"(c[2*jpl+1][0]), "+f"(c[2*jpl+1][1]), "+f"(c[2*jpl+1][2]), "+f"(c[2*jpl+1][3])
                : "r"(a0), "r"(a1), "r"(a2), "r"(a3), "r"(bf.z), "r"(bf.w));
        }
    }

#pragma unroll
    for (int j = 0; j < 8; j++) {
        int col = ch * 64 + j * 8 + tg * 2;
        float2 bb = *reinterpret_cast<const float2*>(&sB[col]);
        float2 e0 = *reinterpret_cast<float2*>(&sA[rloc0 * SSTRIDE + col]);
        float2 e1 = *reinterpret_cast<float2*>(&sA[rloc1 * SSTRIDE + col]);
        float2 o0, o1;
        o0.x = e0.x * sigmoid_t(c[j][0] + bb.x);
        o0.y = e0.y * sigmoid_t(c[j][1] + bb.y);
        o1.x = e1.x * sigmoid_t(c[j][2] + bb.x);
        o1.y = e1.y * sigmoid_t(c[j][3] + bb.y);
        *reinterpret_cast<float2*>(&sA[rloc0 * SSTRIDE + col]) = o0;
        *reinterpret_cast<float2*>(&sA[rloc1 * SSTRIDE + col]) = o1;
    }
    __syncthreads();

#pragma unroll
    for (int r = 0; r < 8; r++) {
        int grow = row0 + warpid * 8 + r;
        if (grow >= n) break;
        float4 o = *reinterpret_cast<float4*>(&sA[(warpid * 8 + r) * SSTRIDE + lane * 4]);
        *(reinterpret_cast<float4*>(acc + (size_t)grow * EMB) + lane) = o;
        __half2 h0 = __floats2half2_rn(o.x, o.y);
        __half2 h1 = __floats2half2_rn(o.z, o.w);
        uint2 hw;
        hw.x = h2u(h0);
        hw.y = h2u(h1);
        *(reinterpret_cast<uint2*>(u + (size_t)grow * EMB) + lane) = hw;
    }
}

// ---------------- fused SpMM + L2-normalize (deferred accumulate) -----------
// R9's exact mainloop: 16/8/tail batches, no cross-iteration prefetch.
__global__ void __launch_bounds__(256)
spmm_fused_kernel(const int* __restrict__ rs,
                  const int2* __restrict__ scv,
                  const __half* __restrict__ x,
                  __half* __restrict__ unext,
                  float* __restrict__ invout,
                  const float* __restrict__ invprev,
                  float* __restrict__ acc,
                  int n) {
    int row = (int)((blockIdx.x * (unsigned)blockDim.x + threadIdx.x) >> 5);
    int lane = threadIdx.x & 31;
    if (row >= n) return;

    const int ehalf = lane >> 4;
    const int fc    = lane & 15;

    int start = __ldg(rs + row);
    int deg   = __ldg(rs + row + 1) - start;

    float s[8];
#pragma unroll
    for (int i = 0; i < 8; i++) s[i] = 0.f;

    int j = 0;
    // 16-edge batches: 8 independent gathers in flight per lane
    for (; j + 16 <= deg; j += 16) {
        int2 cv[8];
#pragma unroll
        for (int i = 0; i < 8; i++)
            cv[i] = __ldg(scv + start + j + 2 * i + ehalf);
        uint4 xv[8];
#pragma unroll
        for (int i = 0; i < 8; i++)
            xv[i] = __ldg(reinterpret_cast<const uint4*>(x + (size_t)cv[i].x * EMB) + fc);
#pragma unroll
        for (int i = 0; i < 8; i++) {
            float v = __int_as_float(cv[i].y);
            const __half2* hp = reinterpret_cast<const __half2*>(&xv[i]);
            float2 f0 = __half22float2(hp[0]);
            float2 f1 = __half22float2(hp[1]);
            float2 f2 = __half22float2(hp[2]);
            float2 f3 = __half22float2(hp[3]);
            s[0] = fmaf(v, f0.x, s[0]); s[1] = fmaf(v, f0.y, s[1]);
            s[2] = fmaf(v, f1.x, s[2]); s[3] = fmaf(v, f1.y, s[3]);
            s[4] = fmaf(v, f2.x, s[4]); s[5] = fmaf(v, f2.y, s[5]);
            s[6] = fmaf(v, f3.x, s[6]); s[7] = fmaf(v, f3.y, s[7]);
        }
    }
    // 8-edge batch
    if (j + 8 <= deg) {
        int2 cv[4];
#pragma unroll
        for (int i = 0; i < 4; i++)
            cv[i] = __ldg(scv + start + j + 2 * i + ehalf);
        uint4 xv[4];
#pragma unroll
        for (int i = 0; i < 4; i++)
            xv[i] = __ldg(reinterpret_cast<const uint4*>(x + (size_t)cv[i].x * EMB) + fc);
#pragma unroll
        for (int i = 0; i < 4; i++) {
            float v = __int_as_float(cv[i].y);
            const __half2* hp = reinterpret_cast<const __half2*>(&xv[i]);
            float2 f0 = __half22float2(hp[0]);
            float2 f1 = __half22float2(hp[1]);
            float2 f2 = __half22float2(hp[2]);
            float2 f3 = __half22float2(hp[3]);
            s[0] = fmaf(v, f0.x, s[0]); s[1] = fmaf(v, f0.y, s[1]);
            s[2] = fmaf(v, f1.x, s[2]); s[3] = fmaf(v, f1.y, s[3]);
            s[4] = fmaf(v, f2.x, s[4]); s[5] = fmaf(v, f2.y, s[5]);
            s[6] = fmaf(v, f3.x, s[6]); s[7] = fmaf(v, f3.y, s[7]);
        }
        j += 8;
    }
    // tail pairs
    for (; j < deg; j += 2) {
        int e = j + ehalf;
        int2 cv = (e < deg) ? __ldg(scv + start + e) : make_int2(0, 0);
        float v = __int_as_float(cv.y);
        uint4 xv = __ldg(reinterpret_cast<const uint4*>(x + (size_t)cv.x * EMB) + fc);
        const __half2* hp = reinterpret_cast<const __half2*>(&xv);
        float2 f0 = __half22float2(hp[0]);
        float2 f1 = __half22float2(hp[1]);
        float2 f2 = __half22float2(hp[2]);
        float2 f3 = __half22float2(hp[3]);
        s[0] = fmaf(v, f0.x, s[0]); s[1] = fmaf(v, f0.y, s[1]);
        s[2] = fmaf(v, f1.x, s[2]); s[3] = fmaf(v, f1.y, s[3]);
        s[4] = fmaf(v, f2.x, s[4]); s[5] = fmaf(v, f2.y, s[5]);
        s[6] = fmaf(v, f3.x, s[6]); s[7] = fmaf(v, f3.y, s[7]);
    }

#pragma unroll
    for (int i = 0; i < 8; i++)
        s[i] += __shfl_xor_sync(0xFFFFFFFFu, s[i], 16);

    float ss = s[0] * s[0] + s[1] * s[1] + s[2] * s[2] + s[3] * s[3]
             + s[4] * s[4] + s[5] * s[5] + s[6] * s[6] + s[7] * s[7];
#pragma unroll
    for (int o = 1; o < 16; o <<= 1) ss += __shfl_xor_sync(0xFFFFFFFFu, ss, o);
    float inv = 1.f / fmaxf(sqrtf(ss), 1e-12f);

    if (unext) {
        if (ehalf == 0) {
            __half2 h0 = __floats2half2_rn(s[0], s[1]);
            __half2 h1 = __floats2half2_rn(s[2], s[3]);
            __half2 h2 = __floats2half2_rn(s[4], s[5]);
            __half2 h3 = __floats2half2_rn(s[6], s[7]);
            uint4 hw;
            hw.x = h2u(h0); hw.y = h2u(h1);
            hw.z = h2u(h2); hw.w = h2u(h3);
            *(reinterpret_cast<uint4*>(unext + (size_t)row * EMB) + fc) = hw;
        }
        if (lane == 0) invout[row] = inv;
    } else {
        float ip = __ldg(invprev + row);
        int fbase = fc * 8 + ehalf * 4;
        const float* sp = s + ehalf * 4;
        uint2 raw = __ldg(reinterpret_cast<const uint2*>(x + (size_t)row * EMB + fbase));
        __half2 u1h0 = *reinterpret_cast<__half2*>(&raw.x);
        __half2 u1h1 = *reinterpret_cast<__half2*>(&raw.y);
        float2 u1f0 = __half22float2(u1h0);
        float2 u1f1 = __half22float2(u1h1);
        float4* ap = reinterpret_cast<float4*>(acc + (size_t)row * EMB + fbase);
        float4 a = *ap;
        a.x = fmaf(ip, u1f0.x, fmaf(sp[0], inv, a.x));
        a.y = fmaf(ip, u1f0.y, fmaf(sp[1], inv, a.y));
        a.z = fmaf(ip, u1f1.x, fmaf(sp[2], inv, a.z));
        a.w = fmaf(ip, u1f1.y, fmaf(sp[3], inv, a.w));
        *ap = a;
    }
}

// ---------------- launch -----------------------------------------------------
extern "C" void kernel_launch(void* const* d_in, const int* in_sizes, int n_in,
                              void* d_out, int out_size) {
    const float* emb  = (const float*)d_in[0];
    const float* W    = (const float*)d_in[1];
    const float* bias = (const float*)d_in[2];
    const int*   rows = (const int*)  d_in[3];
    const int*   cols = (const int*)  d_in[4];
    const float* vals = (const float*)d_in[5];

    int n   = in_sizes[0] / EMB;
    int nnz = in_sizes[3];
    float* acc = (float*)d_out;

    __half *bufA, *bufB;
    int *csrws, *rs, *cur;
    int2 *scv;
    uint4 *wfrag;
    float *invb;
    cudaGetSymbolAddress((void**)&bufA,  g_bufA);
    cudaGetSymbolAddress((void**)&bufB,  g_bufB);
    cudaGetSymbolAddress((void**)&csrws, g_csrws);
    cudaGetSymbolAddress((void**)&rs,    g_rs);
    cudaGetSymbolAddress((void**)&cur,   g_cur);
    cudaGetSymbolAddress((void**)&scv,   g_scv);
    cudaGetSymbolAddress((void**)&wfrag, g_wfrag);
    cudaGetSymbolAddress((void**)&invb,  g_inv);

    int* cnt = csrws;
    unsigned long long* stat = (unsigned long long*)(csrws + n);
    int* ticket = csrws + n + 52;
    int* done   = csrws + n + 53;

    // K1: hist + W-fragment transpose
    hist_wtrans_kernel<<<8 + (nnz + 255) / 256, 256>>>(rows, cnt, nnz, W, wfrag);

    // K2: scan (self-cleaning)
    int nb = (n + 4095) / 4096;
    scan_kernel<<<nb, 1024>>>(cnt, rs, cur, stat, ticket, done, n);

    // K3: scatter
    scatter_kernel<<<(nnz + 255) / 256, 256>>>(rows, cols, vals, cur, scv, nnz);

    // K4: gate (u0 -> bufA fp16, acc = u0 fp32)
    int smem_bytes = 64 * SSTRIDE * sizeof(float);
    cudaFuncSetAttribute(gate_mma_kernel,
                         cudaFuncAttributeMaxDynamicSharedMemorySize, smem_bytes);
    gate_mma_kernel<<<(n + 63) / 64, 256, smem_bytes>>>(emb, wfrag, bias, bufA, acc, n);

    // K5/K6: fused spmm layers
    unsigned spmm_blocks = (unsigned)(((size_t)n * 32 + 255) / 256);
    spmm_fused_kernel<<<spmm_blocks, 256>>>(rs, scv, bufA, bufB, invb, nullptr, nullptr, n);
    spmm_fused_kernel<<<spmm_blocks, 256>>>(rs, scv, bufB, nullptr, nullptr, invb, acc, n);
}

// round 15
// speedup vs baseline: 1.1627x; 1.0717x over previous
#include <cuda_runtime.h>
#include <cuda_fp16.h>
#include <cstdint>

#define EMB 128
#define MAX_NODES 100000
#define MAX_EDGES 1600000
#define SSTRIDE 132   // padded smem row stride (floats): conflict-free frag reads

// ---------------- scratch (static device globals: allocation-guard safe) ----
__device__ __half g_bufA[(size_t)MAX_NODES * EMB];
__device__ __half g_bufB[(size_t)MAX_NODES * EMB];
__device__ int    g_csrws[MAX_NODES + 64];   // cnt | stat(52) | ticket | done
__device__ int    g_rs[MAX_NODES + 1];
__device__ int    g_cur[MAX_NODES];
__device__ float  g_inv[MAX_NODES];
__device__ int2   g_scv[MAX_EDGES];          // (col, val bits)
__device__ uint4  g_wfrag[8 * 8 * 32];       // fp16 B-fragments, j-pair packed (32 KB)

__device__ __forceinline__ float sigmoid_t(float z) {
    float t;
    asm("tanh.approx.f32 %0, %1;" : "=f"(t) : "f"(0.5f * z));
    return fmaf(0.5f, t, 0.5f);
}

__device__ __forceinline__ unsigned int h2u(__half2 h) {
    return *reinterpret_cast<unsigned int*>(&h);
}

// ---------------- W-fragment transpose (tiny, before the fork) ---------------
__global__ void wtrans_kernel(const float* __restrict__ W,
                              uint4* __restrict__ wfrag) {
    int id = blockIdx.x * 256 + threadIdx.x;    // 0..2047
    int lane = id & 31;
    int jp = (id >> 5) & 7;
    int kk = id >> 8;
    int g  = lane >> 2;
    int tg = lane & 3;
    int k0 = kk * 16 + tg * 2;
    int col0 = (2 * jp)     * 8 + g;
    int col1 = (2 * jp + 1) * 8 + g;
    __half2 b0j0 = __floats2half2_rn(W[(size_t)k0       * EMB + col0], W[(size_t)(k0 + 1) * EMB + col0]);
    __half2 b1j0 = __floats2half2_rn(W[(size_t)(k0 + 8) * EMB + col0], W[(size_t)(k0 + 9) * EMB + col0]);
    __half2 b0j1 = __floats2half2_rn(W[(size_t)k0       * EMB + col1], W[(size_t)(k0 + 1) * EMB + col1]);
    __half2 b1j1 = __floats2half2_rn(W[(size_t)(k0 + 8) * EMB + col1], W[(size_t)(k0 + 9) * EMB + col1]);
    uint4 v;
    v.x = h2u(b0j0); v.y = h2u(b1j0);
    v.z = h2u(b0j1); v.w = h2u(b1j1);
    wfrag[id] = v;
}

// ---------------- histogram --------------------------------------------------
__global__ void hist_kernel(const int* __restrict__ rows,
                            int* __restrict__ cnt, int nnz) {
    int e = blockIdx.x * 256 + threadIdx.x;
    if (e < nnz) atomicAdd(&cnt[rows[e]], 1);
}

// ---------------- single-pass decoupled-lookback scan (self-cleaning) --------
__global__ void scan_kernel(int* __restrict__ cnt,
                            int* __restrict__ rs, int* __restrict__ cur,
                            unsigned long long* __restrict__ stat,
                            int* __restrict__ ticket, int* __restrict__ done,
                            int n) {
    __shared__ int sbid;
    __shared__ int warpsum[32];
    __shared__ int sprefix;
    int t = threadIdx.x;
    if (t == 0) sbid = atomicAdd(ticket, 1);
    __syncthreads();
    int bid = sbid;

    int base = bid * 4096 + t * 4;
    int4 c = make_int4(0, 0, 0, 0);
    if (base + 3 < n) {
        c = *reinterpret_cast<const int4*>(cnt + base);
        *reinterpret_cast<int4*>(cnt + base) = make_int4(0, 0, 0, 0);
    } else {
        if (base     < n) { c.x = cnt[base];     cnt[base]     = 0; }
        if (base + 1 < n) { c.y = cnt[base + 1]; cnt[base + 1] = 0; }
        if (base + 2 < n) { c.z = cnt[base + 2]; cnt[base + 2] = 0; }
        if (base + 3 < n) { c.w = cnt[base + 3]; cnt[base + 3] = 0; }
    }
    int tot = c.x + c.y + c.z + c.w;
    int lane = t & 31, wid = t >> 5;
    int inc = tot;
#pragma unroll
    for (int o = 1; o < 32; o <<= 1) {
        int u = __shfl_up_sync(0xFFFFFFFFu, inc, o);
        if (lane >= o) inc += u;
    }
    if (lane == 31) warpsum[wid] = inc;
    __syncthreads();
    if (wid == 0) {
        int w = warpsum[lane];
#pragma unroll
        for (int o = 1; o < 32; o <<= 1) {
            int u = __shfl_up_sync(0xFFFFFFFFu, w, o);
            if (lane >= o) w += u;
        }
        warpsum[lane] = w;
    }
    __syncthreads();
    int blocktot = warpsum[31];
    int excl = inc - tot + (wid ? warpsum[wid - 1] : 0);

    if (t == 0) {
        if (bid == 0) {
            atomicExch(&stat[0], (2ull << 32) | (unsigned)blocktot);
            sprefix = 0;
        } else {
            atomicExch(&stat[bid], (1ull << 32) | (unsigned)blocktot);
            int pre = 0;
            for (int i = bid - 1; i >= 0; i--) {
                unsigned long long s;
                do { s = atomicAdd(&stat[i], 0ull); } while ((s >> 32) == 0ull);
                pre += (int)(unsigned)s;
                if ((s >> 32) == 2ull) break;
            }
            atomicExch(&stat[bid], (2ull << 32) | (unsigned)(pre + blocktot));
            sprefix = pre;
        }
    }
    __syncthreads();
    int prefix = sprefix;

    int v0 = excl + prefix;
    if (base     < n) { rs[base]     = v0;                   cur[base]     = v0; }
    if (base + 1 < n) { rs[base + 1] = v0 + c.x;             cur[base + 1] = v0 + c.x; }
    if (base + 2 < n) { rs[base + 2] = v0 + c.x + c.y;       cur[base + 2] = v0 + c.x + c.y; }
    if (base + 3 < n) { rs[base + 3] = v0 + c.x + c.y + c.z; cur[base + 3] = v0 + c.x + c.y + c.z; }
    if (bid == gridDim.x - 1 && t == 1023) rs[n] = prefix + blocktot;

    __syncthreads();
    if (t == 0) {
        int d = atomicAdd(done, 1);
        if (d == (int)gridDim.x - 1) {
            for (int i = 0; i < (int)gridDim.x; i++) stat[i] = 0ull;
            *ticket = 0;
            *done = 0;
        }
    }
}

__global__ void scatter_kernel(const int* __restrict__ rows,
                               const int* __restrict__ cols,
                               const float* __restrict__ vals,
                               int* __restrict__ cur,
                               int2* __restrict__ scv, int nnz) {
    int e = blockIdx.x * 256 + threadIdx.x;
    if (e >= nnz) return;
    int p = atomicAdd(&cur[rows[e]], 1);
    scv[p] = make_int2(cols[e], __float_as_int(vals[e]));
}

// ---------------- self-gating: fp16 warp-MMA, 64-row tiles ------------------
// __launch_bounds__(256, 4): 64 regs -> 4 resident blocks (measured 40us)
__global__ void __launch_bounds__(256, 4)
gate_mma_kernel(const float* __restrict__ emb,
                const uint4* __restrict__ wfrag,
                const float* __restrict__ b,
                __half* __restrict__ u,
                float* __restrict__ acc,
                int n) {
    extern __shared__ float sA[];              // [64][SSTRIDE]
    __shared__ float sB[EMB];
    const int tx = threadIdx.x;
    const int warpid = tx >> 5;
    const int lane = tx & 31;
    const int row0 = blockIdx.x * 64;

    for (int i = tx; i < 64 * 32; i += 256) {
        int r = i >> 5;
        int cc = (i & 31) * 4;
        float4 v = make_float4(0.f, 0.f, 0.f, 0.f);
        if (row0 + r < n)
            v = *reinterpret_cast<const float4*>(emb + (size_t)(row0 + r) * EMB + cc);
        *reinterpret_cast<float4*>(&sA[r * SSTRIDE + cc]) = v;
    }
    if (tx < 64) {
        float2 bv = __ldg(reinterpret_cast<const float2*>(b) + tx);
        *reinterpret_cast<float2*>(&sB[tx * 2]) = bv;
    }
    __syncthreads();

    const int rowgrp = warpid >> 1;
    const int ch     = warpid & 1;
    const int g  = lane >> 2;
    const int tg = lane & 3;
    const int rloc0 = rowgrp * 16 + g;
    const int rloc1 = rloc0 + 8;

    float c[8][4];
#pragma unroll
    for (int j = 0; j < 8; j++)
#pragma unroll
        for (int q = 0; q < 4; q++) c[j][q] = 0.f;

#pragma unroll
    for (int kk = 0; kk < 8; kk++) {
        int kb = kk * 16;
        float2 f0 = *reinterpret_cast<const float2*>(&sA[rloc0 * SSTRIDE + kb + tg * 2]);
        float2 f1 = *reinterpret_cast<const float2*>(&sA[rloc1 * SSTRIDE + kb + tg * 2]);
        float2 f2 = *reinterpret_cast<const float2*>(&sA[rloc0 * SSTRIDE + kb + tg * 2 + 8]);
        float2 f3 = *reinterpret_cast<const float2*>(&sA[rloc1 * SSTRIDE + kb + tg * 2 + 8]);
        unsigned int a0 = h2u(__floats2half2_rn(f0.x, f0.y));
        unsigned int a1 = h2u(__floats2half2_rn(f1.x, f1.y));
        unsigned int a2 = h2u(__floats2half2_rn(f2.x, f2.y));
        unsigned int a3 = h2u(__floats2half2_rn(f3.x, f3.y));

        const uint4* wfk = wfrag + (size_t)kk * 256 + ch * 128 + lane;
#pragma unroll
        for (int jpl = 0; jpl < 4; jpl++) {
            uint4 bf = __ldg(wfk + jpl * 32);
            asm volatile(
                "mma.sync.aligned.m16n8k16.row.col.f32.f16.f16.f32 "
                "{%0,%1,%2,%3}, {%4,%5,%6,%7}, {%8,%9}, {%0,%1,%2,%3};"
                : "+f"(c[2*jpl][0]), "+f"(c[2*jpl][1]), "+f"(c[2*jpl][2]), "+f"(c[2*jpl][3])
                : "r"(a0), "r"(a1), "r"(a2), "r"(a3), "r"(bf.x), "r"(bf.y));
            asm volatile(
                "mma.sync.aligned.m16n8k16.row.col.f32.f16.f16.f32 "
                "{%0,%1,%2,%3}, {%4,%5,%6,%7}, {%8,%9}, {%0,%1,%2,%3};"
                : "+f"(c[2*jpl+1][0]), "+f"(c[2*jpl+1][1]), "+f"(c[2*jpl+1][2]), "+f"(c[2*jpl+1][3])
                : "r"(a0), "r"(a1), "r"(a2), "r"(a3), "r"(bf.z), "r"(bf.w));
        }
    }

#pragma unroll
    for (int j = 0; j < 8; j++) {
        int col = ch * 64 + j * 8 + tg * 2;
        float2 bb = *reinterpret_cast<const float2*>(&sB[col]);
        float2 e0 = *reinterpret_cast<float2*>(&sA[rloc0 * SSTRIDE + col]);
        float2 e1 = *reinterpret_cast<float2*>(&sA[rloc1 * SSTRIDE + col]);
        float2 o0, o1;
        o0.x = e0.x * sigmoid_t(c[j][0] + bb.x);
        o0.y = e0.y * sigmoid_t(c[j][1] + bb.y);
        o1.x = e1.x * sigmoid_t(c[j][2] + bb.x);
        o1.y = e1.y * sigmoid_t(c[j][3] + bb.y);
        *reinterpret_cast<float2*>(&sA[rloc0 * SSTRIDE + col]) = o0;
        *reinterpret_cast<float2*>(&sA[rloc1 * SSTRIDE + col]) = o1;
    }
    __syncthreads();

#pragma unroll
    for (int r = 0; r < 8; r++) {
        int grow = row0 + warpid * 8 + r;
        if (grow >= n) break;
        float4 o = *reinterpret_cast<float4*>(&sA[(warpid * 8 + r) * SSTRIDE + lane * 4]);
        *(reinterpret_cast<float4*>(acc + (size_t)grow * EMB) + lane) = o;
        __half2 h0 = __floats2half2_rn(o.x, o.y);
        __half2 h1 = __floats2half2_rn(o.z, o.w);
        uint2 hw;
        hw.x = h2u(h0);
        hw.y = h2u(h1);
        *(reinterpret_cast<uint2*>(u + (size_t)grow * EMB) + lane) = hw;
    }
}

// ---------------- fused SpMM + L2-normalize (deferred accumulate) -----------
// R9's exact mainloop: 16/8/tail batches, no cross-iteration prefetch.
__global__ void __launch_bounds__(256)
spmm_fused_kernel(const int* __restrict__ rs,
                  const int2* __restrict__ scv,
                  const __half* __restrict__ x,
                  __half* __restrict__ unext,
                  float* __restrict__ invout,
                  const float* __restrict__ invprev,
                  float* __restrict__ acc,
                  int n) {
    int row = (int)((blockIdx.x * (unsigned)blockDim.x + threadIdx.x) >> 5);
    int lane = threadIdx.x & 31;
    if (row >= n) return;

    const int ehalf = lane >> 4;
    const int fc    = lane & 15;

    int start = __ldg(rs + row);
    int deg   = __ldg(rs + row + 1) - start;

    float s[8];
#pragma unroll
    for (int i = 0; i < 8; i++) s[i] = 0.f;

    int j = 0;
    for (; j + 16 <= deg; j += 16) {
        int2 cv[8];
#pragma unroll
        for (int i = 0; i < 8; i++)
            cv[i] = __ldg(scv + start + j + 2 * i + ehalf);
        uint4 xv[8];
#pragma unroll
        for (int i = 0; i < 8; i++)
            xv[i] = __ldg(reinterpret_cast<const uint4*>(x + (size_t)cv[i].x * EMB) + fc);
#pragma unroll
        for (int i = 0; i < 8; i++) {
            float v = __int_as_float(cv[i].y);
            const __half2* hp = reinterpret_cast<const __half2*>(&xv[i]);
            float2 f0 = __half22float2(hp[0]);
            float2 f1 = __half22float2(hp[1]);
            float2 f2 = __half22float2(hp[2]);
            float2 f3 = __half22float2(hp[3]);
            s[0] = fmaf(v, f0.x, s[0]); s[1] = fmaf(v, f0.y, s[1]);
            s[2] = fmaf(v, f1.x, s[2]); s[3] = fmaf(v, f1.y, s[3]);
            s[4] = fmaf(v, f2.x, s[4]); s[5] = fmaf(v, f2.y, s[5]);
            s[6] = fmaf(v, f3.x, s[6]); s[7] = fmaf(v, f3.y, s[7]);
        }
    }
    if (j + 8 <= deg) {
        int2 cv[4];
#pragma unroll
        for (int i = 0; i < 4; i++)
            cv[i] = __ldg(scv + start + j + 2 * i + ehalf);
        uint4 xv[4];
#pragma unroll
        for (int i = 0; i < 4; i++)
            xv[i] = __ldg(reinterpret_cast<const uint4*>(x + (size_t)cv[i].x * EMB) + fc);
#pragma unroll
        for (int i = 0; i < 4; i++) {
            float v = __int_as_float(cv[i].y);
            const __half2* hp = reinterpret_cast<const __half2*>(&xv[i]);
            float2 f0 = __half22float2(hp[0]);
            float2 f1 = __half22float2(hp[1]);
            float2 f2 = __half22float2(hp[2]);
            float2 f3 = __half22float2(hp[3]);
            s[0] = fmaf(v, f0.x, s[0]); s[1] = fmaf(v, f0.y, s[1]);
            s[2] = fmaf(v, f1.x, s[2]); s[3] = fmaf(v, f1.y, s[3]);
            s[4] = fmaf(v, f2.x, s[4]); s[5] = fmaf(v, f2.y, s[5]);
            s[6] = fmaf(v, f3.x, s[6]); s[7] = fmaf(v, f3.y, s[7]);
        }
        j += 8;
    }
    for (; j < deg; j += 2) {
        int e = j + ehalf;
        int2 cv = (e < deg) ? __ldg(scv + start + e) : make_int2(0, 0);
        float v = __int_as_float(cv.y);
        uint4 xv = __ldg(reinterpret_cast<const uint4*>(x + (size_t)cv.x * EMB) + fc);
        const __half2* hp = reinterpret_cast<const __half2*>(&xv);
        float2 f0 = __half22float2(hp[0]);
        float2 f1 = __half22float2(hp[1]);
        float2 f2 = __half22float2(hp[2]);
        float2 f3 = __half22float2(hp[3]);
        s[0] = fmaf(v, f0.x, s[0]); s[1] = fmaf(v, f0.y, s[1]);
        s[2] = fmaf(v, f1.x, s[2]); s[3] = fmaf(v, f1.y, s[3]);
        s[4] = fmaf(v, f2.x, s[4]); s[5] = fmaf(v, f2.y, s[5]);
        s[6] = fmaf(v, f3.x, s[6]); s[7] = fmaf(v, f3.y, s[7]);
    }

#pragma unroll
    for (int i = 0; i < 8; i++)
        s[i] += __shfl_xor_sync(0xFFFFFFFFu, s[i], 16);

    float ss = s[0] * s[0] + s[1] * s[1] + s[2] * s[2] + s[3] * s[3]
             + s[4] * s[4] + s[5] * s[5] + s[6] * s[6] + s[7] * s[7];
#pragma unroll
    for (int o = 1; o < 16; o <<= 1) ss += __shfl_xor_sync(0xFFFFFFFFu, ss, o);
    float inv = 1.f / fmaxf(sqrtf(ss), 1e-12f);

    if (unext) {
        if (ehalf == 0) {
            __half2 h0 = __floats2half2_rn(s[0], s[1]);
            __half2 h1 = __floats2half2_rn(s[2], s[3]);
            __half2 h2 = __floats2half2_rn(s[4], s[5]);
            __half2 h3 = __floats2half2_rn(s[6], s[7]);
            uint4 hw;
            hw.x = h2u(h0); hw.y = h2u(h1);
            hw.z = h2u(h2); hw.w = h2u(h3);
            *(reinterpret_cast<uint4*>(unext + (size_t)row * EMB) + fc) = hw;
        }
        if (lane == 0) invout[row] = inv;
    } else {
        float ip = __ldg(invprev + row);
        int fbase = fc * 8 + ehalf * 4;
        const float* sp = s + ehalf * 4;
        uint2 raw = __ldg(reinterpret_cast<const uint2*>(x + (size_t)row * EMB + fbase));
        __half2 u1h0 = *reinterpret_cast<__half2*>(&raw.x);
        __half2 u1h1 = *reinterpret_cast<__half2*>(&raw.y);
        float2 u1f0 = __half22float2(u1h0);
        float2 u1f1 = __half22float2(u1h1);
        float4* ap = reinterpret_cast<float4*>(acc + (size_t)row * EMB + fbase);
        float4 a = *ap;
        a.x = fmaf(ip, u1f0.x, fmaf(sp[0], inv, a.x));
        a.y = fmaf(ip, u1f0.y, fmaf(sp[1], inv, a.y));
        a.z = fmaf(ip, u1f1.x, fmaf(sp[2], inv, a.z));
        a.w = fmaf(ip, u1f1.y, fmaf(sp[3], inv, a.w));
        *ap = a;
    }
}

// ---------------- launch -----------------------------------------------------
static cudaStream_t g_side = nullptr;
static cudaEvent_t  g_evFork = nullptr, g_evGate = nullptr;

extern "C" void kernel_launch(void* const* d_in, const int* in_sizes, int n_in,
                              void* d_out, int out_size) {
    const float* emb  = (const float*)d_in[0];
    const float* W    = (const float*)d_in[1];
    const float* bias = (const float*)d_in[2];
    const int*   rows = (const int*)  d_in[3];
    const int*   cols = (const int*)  d_in[4];
    const float* vals = (const float*)d_in[5];

    int n   = in_sizes[0] / EMB;
    int nnz = in_sizes[3];
    float* acc = (float*)d_out;

    __half *bufA, *bufB;
    int *csrws, *rs, *cur;
    int2 *scv;
    uint4 *wfrag;
    float *invb;
    cudaGetSymbolAddress((void**)&bufA,  g_bufA);
    cudaGetSymbolAddress((void**)&bufB,  g_bufB);
    cudaGetSymbolAddress((void**)&csrws, g_csrws);
    cudaGetSymbolAddress((void**)&rs,    g_rs);
    cudaGetSymbolAddress((void**)&cur,   g_cur);
    cudaGetSymbolAddress((void**)&scv,   g_scv);
    cudaGetSymbolAddress((void**)&wfrag, g_wfrag);
    cudaGetSymbolAddress((void**)&invb,  g_inv);

    int* cnt = csrws;
    unsigned long long* stat = (unsigned long long*)(csrws + n);
    int* ticket = csrws + n + 52;
    int* done   = csrws + n + 53;

    if (!g_side) {   // resource init only (first, uncaptured call); no work cached
        cudaStreamCreateWithFlags(&g_side, cudaStreamNonBlocking);
        cudaEventCreateWithFlags(&g_evFork, cudaEventDisableTiming);
        cudaEventCreateWithFlags(&g_evGate, cudaEventDisableTiming);
    }

    int smem_bytes = 64 * SSTRIDE * sizeof(float);
    cudaFuncSetAttribute(gate_mma_kernel,
                         cudaFuncAttributeMaxDynamicSharedMemorySize, smem_bytes);

    // K1 (main): W-fragment transpose (gate's only dependency besides emb)
    wtrans_kernel<<<8, 256>>>(W, wfrag);

    // fork: gate on side stream, overlapped with CSR build on main
    cudaEventRecord(g_evFork, 0);
    cudaStreamWaitEvent(g_side, g_evFork, 0);
    gate_mma_kernel<<<(n + 63) / 64, 256, smem_bytes, g_side>>>(
        emb, wfrag, bias, bufA, acc, n);
    cudaEventRecord(g_evGate, g_side);

    // main: hist -> scan -> scatter
    hist_kernel<<<(nnz + 255) / 256, 256>>>(rows, cnt, nnz);
    int nb = (n + 4095) / 4096;
    scan_kernel<<<nb, 1024>>>(cnt, rs, cur, stat, ticket, done, n);
    scatter_kernel<<<(nnz + 255) / 256, 256>>>(rows, cols, vals, cur, scv, nnz);

    // join: spmm needs bufA (gate) + scv (scatter)
    cudaStreamWaitEvent(0, g_evGate, 0);

    unsigned spmm_blocks = (unsigned)(((size_t)n * 32 + 255) / 256);
    spmm_fused_kernel<<<spmm_blocks, 256>>>(rs, scv, bufA, bufB, invb, nullptr, nullptr, n);
    spmm_fused_kernel<<<spmm_blocks, 256>>>(rs, scv, bufB, nullptr, nullptr, invb, acc, n);
}

// round 16
// speedup vs baseline: 1.1922x; 1.0253x over previous
#include <cuda_runtime.h>
#include <cuda_fp16.h>
#include <cstdint>

#define EMB 128
#define MAX_NODES 100000
#define MAX_EDGES 1600000
#define HSTRIDE 136   // fp16 smem row stride (halfs): bank = (4g+tg+8kk)%32, conflict-free

// ---------------- scratch (static device globals: allocation-guard safe) ----
__device__ __half g_bufA[(size_t)MAX_NODES * EMB];
__device__ __half g_bufB[(size_t)MAX_NODES * EMB];
__device__ int    g_csrws[MAX_NODES + 64];   // cnt | stat(52) | ticket | done
__device__ int    g_rs[MAX_NODES + 1];
__device__ int    g_cur[MAX_NODES];
__device__ float  g_inv[MAX_NODES];
__device__ int2   g_scv[MAX_EDGES];          // (col, val bits)
__device__ uint4  g_wfrag[8 * 8 * 32];       // fp16 B-fragments, j-pair packed (32 KB)

__device__ __forceinline__ float sigmoid_t(float z) {
    float t;
    asm("tanh.approx.f32 %0, %1;" : "=f"(t) : "f"(0.5f * z));
    return fmaf(0.5f, t, 0.5f);
}

__device__ __forceinline__ unsigned int h2u(__half2 h) {
    return *reinterpret_cast<unsigned int*>(&h);
}

// ---------------- W-fragment transpose (tiny, before the fork) ---------------
__global__ void wtrans_kernel(const float* __restrict__ W,
                              uint4* __restrict__ wfrag) {
    int id = blockIdx.x * 256 + threadIdx.x;    // 0..2047
    int lane = id & 31;
    int jp = (id >> 5) & 7;
    int kk = id >> 8;
    int g  = lane >> 2;
    int tg = lane & 3;
    int k0 = kk * 16 + tg * 2;
    int col0 = (2 * jp)     * 8 + g;
    int col1 = (2 * jp + 1) * 8 + g;
    __half2 b0j0 = __floats2half2_rn(W[(size_t)k0       * EMB + col0], W[(size_t)(k0 + 1) * EMB + col0]);
    __half2 b1j0 = __floats2half2_rn(W[(size_t)(k0 + 8) * EMB + col0], W[(size_t)(k0 + 9) * EMB + col0]);
    __half2 b0j1 = __floats2half2_rn(W[(size_t)k0       * EMB + col1], W[(size_t)(k0 + 1) * EMB + col1]);
    __half2 b1j1 = __floats2half2_rn(W[(size_t)(k0 + 8) * EMB + col1], W[(size_t)(k0 + 9) * EMB + col1]);
    uint4 v;
    v.x = h2u(b0j0); v.y = h2u(b1j0);
    v.z = h2u(b0j1); v.w = h2u(b1j1);
    wfrag[id] = v;
}

// ---------------- histogram --------------------------------------------------
__global__ void hist_kernel(const int* __restrict__ rows,
                            int* __restrict__ cnt, int nnz) {
    int e = blockIdx.x * 256 + threadIdx.x;
    if (e < nnz) atomicAdd(&cnt[rows[e]], 1);
}

// ---------------- single-pass decoupled-lookback scan (self-cleaning) --------
__global__ void scan_kernel(int* __restrict__ cnt,
                            int* __restrict__ rs, int* __restrict__ cur,
                            unsigned long long* __restrict__ stat,
                            int* __restrict__ ticket, int* __restrict__ done,
                            int n) {
    __shared__ int sbid;
    __shared__ int warpsum[32];
    __shared__ int sprefix;
    int t = threadIdx.x;
    if (t == 0) sbid = atomicAdd(ticket, 1);
    __syncthreads();
    int bid = sbid;

    int base = bid * 4096 + t * 4;
    int4 c = make_int4(0, 0, 0, 0);
    if (base + 3 < n) {
        c = *reinterpret_cast<const int4*>(cnt + base);
        *reinterpret_cast<int4*>(cnt + base) = make_int4(0, 0, 0, 0);
    } else {
        if (base     < n) { c.x = cnt[base];     cnt[base]     = 0; }
        if (base + 1 < n) { c.y = cnt[base + 1]; cnt[base + 1] = 0; }
        if (base + 2 < n) { c.z = cnt[base + 2]; cnt[base + 2] = 0; }
        if (base + 3 < n) { c.w = cnt[base + 3]; cnt[base + 3] = 0; }
    }
    int tot = c.x + c.y + c.z + c.w;
    int lane = t & 31, wid = t >> 5;
    int inc = tot;
#pragma unroll
    for (int o = 1; o < 32; o <<= 1) {
        int u = __shfl_up_sync(0xFFFFFFFFu, inc, o);
        if (lane >= o) inc += u;
    }
    if (lane == 31) warpsum[wid] = inc;
    __syncthreads();
    if (wid == 0) {
        int w = warpsum[lane];
#pragma unroll
        for (int o = 1; o < 32; o <<= 1) {
            int u = __shfl_up_sync(0xFFFFFFFFu, w, o);
            if (lane >= o) w += u;
        }
        warpsum[lane] = w;
    }
    __syncthreads();
    int blocktot = warpsum[31];
    int excl = inc - tot + (wid ? warpsum[wid - 1] : 0);

    if (t == 0) {
        if (bid == 0) {
            atomicExch(&stat[0], (2ull << 32) | (unsigned)blocktot);
            sprefix = 0;
        } else {
            atomicExch(&stat[bid], (1ull << 32) | (unsigned)blocktot);
            int pre = 0;
            for (int i = bid - 1; i >= 0; i--) {
                unsigned long long s;
                do { s = atomicAdd(&stat[i], 0ull); } while ((s >> 32) == 0ull);
                pre += (int)(unsigned)s;
                if ((s >> 32) == 2ull) break;
            }
            atomicExch(&stat[bid], (2ull << 32) | (unsigned)(pre + blocktot));
            sprefix = pre;
        }
    }
    __syncthreads();
    int prefix = sprefix;

    int v0 = excl + prefix;
    if (base     < n) { rs[base]     = v0;                   cur[base]     = v0; }
    if (base + 1 < n) { rs[base + 1] = v0 + c.x;             cur[base + 1] = v0 + c.x; }
    if (base + 2 < n) { rs[base + 2] = v0 + c.x + c.y;       cur[base + 2] = v0 + c.x + c.y; }
    if (base + 3 < n) { rs[base + 3] = v0 + c.x + c.y + c.z; cur[base + 3] = v0 + c.x + c.y + c.z; }
    if (bid == gridDim.x - 1 && t == 1023) rs[n] = prefix + blocktot;

    __syncthreads();
    if (t == 0) {
        int d = atomicAdd(done, 1);
        if (d == (int)gridDim.x - 1) {
            for (int i = 0; i < (int)gridDim.x; i++) stat[i] = 0ull;
            *ticket = 0;
            *done = 0;
        }
    }
}

__global__ void scatter_kernel(const int* __restrict__ rows,
                               const int* __restrict__ cols,
                               const float* __restrict__ vals,
                               int* __restrict__ cur,
                               int2* __restrict__ scv, int nnz) {
    int e = blockIdx.x * 256 + threadIdx.x;
    if (e >= nnz) return;
    int p = atomicAdd(&cur[rows[e]], 1);
    scv[p] = make_int2(cols[e], __float_as_int(vals[e]));
}

// ---------------- self-gating: fp16 warp-MMA, fp16 smem staging -------------
// 64-row tiles, 8 warps (rowgrp x colhalf). smem 64x136 half = 17.4 KB.
__global__ void __launch_bounds__(256, 4)
gate_mma_kernel(const float* __restrict__ emb,
                const uint4* __restrict__ wfrag,
                const float* __restrict__ b,
                __half* __restrict__ u,
                float* __restrict__ acc,
                int n) {
    extern __shared__ __half sA[];             // [64][HSTRIDE] fp16
    __shared__ float sB[EMB];
    const int tx = threadIdx.x;
    const int warpid = tx >> 5;
    const int lane = tx & 31;
    const int row0 = blockIdx.x * 64;

    // stage emb tile fp32 -> fp16 (coalesced float4 loads, uint2 smem stores)
    for (int i = tx; i < 64 * 32; i += 256) {
        int r = i >> 5;
        int cc = (i & 31) * 4;
        float4 v = make_float4(0.f, 0.f, 0.f, 0.f);
        if (row0 + r < n)
            v = *reinterpret_cast<const float4*>(emb + (size_t)(row0 + r) * EMB + cc);
        __half2 h0 = __floats2half2_rn(v.x, v.y);
        __half2 h1 = __floats2half2_rn(v.z, v.w);
        uint2 hw; hw.x = h2u(h0); hw.y = h2u(h1);
        *reinterpret_cast<uint2*>(&sA[r * HSTRIDE + cc]) = hw;
    }
    if (tx < 64) {
        float2 bv = __ldg(reinterpret_cast<const float2*>(b) + tx);
        *reinterpret_cast<float2*>(&sB[tx * 2]) = bv;
    }
    __syncthreads();

    const int rowgrp = warpid >> 1;
    const int ch     = warpid & 1;
    const int g  = lane >> 2;
    const int tg = lane & 3;
    const int rloc0 = rowgrp * 16 + g;
    const int rloc1 = rloc0 + 8;

    float c[8][4];
#pragma unroll
    for (int j = 0; j < 8; j++)
#pragma unroll
        for (int q = 0; q < 4; q++) c[j][q] = 0.f;

#pragma unroll
    for (int kk = 0; kk < 8; kk++) {
        int kb = kk * 16;
        // A fragments: direct half2 LDS (conflict-free: bank=(4g+tg+8kk)%32)
        unsigned int a0 = *reinterpret_cast<const unsigned int*>(&sA[rloc0 * HSTRIDE + kb + tg * 2]);
        unsigned int a1 = *reinterpret_cast<const unsigned int*>(&sA[rloc1 * HSTRIDE + kb + tg * 2]);
        unsigned int a2 = *reinterpret_cast<const unsigned int*>(&sA[rloc0 * HSTRIDE + kb + tg * 2 + 8]);
        unsigned int a3 = *reinterpret_cast<const unsigned int*>(&sA[rloc1 * HSTRIDE + kb + tg * 2 + 8]);

        const uint4* wfk = wfrag + (size_t)kk * 256 + ch * 128 + lane;
#pragma unroll
        for (int jpl = 0; jpl < 4; jpl++) {
            uint4 bf = __ldg(wfk + jpl * 32);
            asm volatile(
                "mma.sync.aligned.m16n8k16.row.col.f32.f16.f16.f32 "
                "{%0,%1,%2,%3}, {%4,%5,%6,%7}, {%8,%9}, {%0,%1,%2,%3};"
                : "+f"(c[2*jpl][0]), "+f"(c[2*jpl][1]), "+f"(c[2*jpl][2]), "+f"(c[2*jpl][3])
                : "r"(a0), "r"(a1), "r"(a2), "r"(a3), "r"(bf.x), "r"(bf.y));
            asm volatile(
                "mma.sync.aligned.m16n8k16.row.col.f32.f16.f16.f32 "
                "{%0,%1,%2,%3}, {%4,%5,%6,%7}, {%8,%9}, {%0,%1,%2,%3};"
                : "+f"(c[2*jpl+1][0]), "+f"(c[2*jpl+1][1]), "+f"(c[2*jpl+1][2]), "+f"(c[2*jpl+1][3])
                : "r"(a0), "r"(a1), "r"(a2), "r"(a3), "r"(bf.z), "r"(bf.w));
        }
    }

    // gated transpose IN PLACE: read e (half2), gate in fp32, write o back (half2)
#pragma unroll
    for (int j = 0; j < 8; j++) {
        int col = ch * 64 + j * 8 + tg * 2;
        float2 bb = *reinterpret_cast<const float2*>(&sB[col]);
        __half2* p0 = reinterpret_cast<__half2*>(&sA[rloc0 * HSTRIDE + col]);
        __half2* p1 = reinterpret_cast<__half2*>(&sA[rloc1 * HSTRIDE + col]);
        float2 e0 = __half22float2(*p0);
        float2 e1 = __half22float2(*p1);
        float2 o0, o1;
        o0.x = e0.x * sigmoid_t(c[j][0] + bb.x);
        o0.y = e0.y * sigmoid_t(c[j][1] + bb.y);
        o1.x = e1.x * sigmoid_t(c[j][2] + bb.x);
        o1.y = e1.y * sigmoid_t(c[j][3] + bb.y);
        *p0 = __floats2half2_rn(o0.x, o0.y);
        *p1 = __floats2half2_rn(o1.x, o1.y);
    }
    __syncthreads();

    // stream rows: u = raw fp16 copy; acc = fp32 converts
#pragma unroll
    for (int r = 0; r < 8; r++) {
        int grow = row0 + warpid * 8 + r;
        if (grow >= n) break;
        uint2 hw = *reinterpret_cast<const uint2*>(&sA[(warpid * 8 + r) * HSTRIDE + lane * 4]);
        *(reinterpret_cast<uint2*>(u + (size_t)grow * EMB) + lane) = hw;
        __half2 h0 = *reinterpret_cast<__half2*>(&hw.x);
        __half2 h1 = *reinterpret_cast<__half2*>(&hw.y);
        float2 f0 = __half22float2(h0);
        float2 f1 = __half22float2(h1);
        float4 o = make_float4(f0.x, f0.y, f1.x, f1.y);
        *(reinterpret_cast<float4*>(acc + (size_t)grow * EMB) + lane) = o;
    }
}

// ---------------- fused SpMM + L2-normalize (deferred accumulate) -----------
// R9's exact mainloop: 16/8/tail batches, no cross-iteration prefetch. (FROZEN)
__global__ void __launch_bounds__(256)
spmm_fused_kernel(const int* __restrict__ rs,
                  const int2* __restrict__ scv,
                  const __half* __restrict__ x,
                  __half* __restrict__ unext,
                  float* __restrict__ invout,
                  const float* __restrict__ invprev,
                  float* __restrict__ acc,
                  int n) {
    int row = (int)((blockIdx.x * (unsigned)blockDim.x + threadIdx.x) >> 5);
    int lane = threadIdx.x & 31;
    if (row >= n) return;

    const int ehalf = lane >> 4;
    const int fc    = lane & 15;

    int start = __ldg(rs + row);
    int deg   = __ldg(rs + row + 1) - start;

    float s[8];
#pragma unroll
    for (int i = 0; i < 8; i++) s[i] = 0.f;

    int j = 0;
    for (; j + 16 <= deg; j += 16) {
        int2 cv[8];
#pragma unroll
        for (int i = 0; i < 8; i++)
            cv[i] = __ldg(scv + start + j + 2 * i + ehalf);
        uint4 xv[8];
#pragma unroll
        for (int i = 0; i < 8; i++)
            xv[i] = __ldg(reinterpret_cast<const uint4*>(x + (size_t)cv[i].x * EMB) + fc);
#pragma unroll
        for (int i = 0; i < 8; i++) {
            float v = __int_as_float(cv[i].y);
            const __half2* hp = reinterpret_cast<const __half2*>(&xv[i]);
            float2 f0 = __half22float2(hp[0]);
            float2 f1 = __half22float2(hp[1]);
            float2 f2 = __half22float2(hp[2]);
            float2 f3 = __half22float2(hp[3]);
            s[0] = fmaf(v, f0.x, s[0]); s[1] = fmaf(v, f0.y, s[1]);
            s[2] = fmaf(v, f1.x, s[2]); s[3] = fmaf(v, f1.y, s[3]);
            s[4] = fmaf(v, f2.x, s[4]); s[5] = fmaf(v, f2.y, s[5]);
            s[6] = fmaf(v, f3.x, s[6]); s[7] = fmaf(v, f3.y, s[7]);
        }
    }
    if (j + 8 <= deg) {
        int2 cv[4];
#pragma unroll
        for (int i = 0; i < 4; i++)
            cv[i] = __ldg(scv + start + j + 2 * i + ehalf);
        uint4 xv[4];
#pragma unroll
        for (int i = 0; i < 4; i++)
            xv[i] = __ldg(reinterpret_cast<const uint4*>(x + (size_t)cv[i].x * EMB) + fc);
#pragma unroll
        for (int i = 0; i < 4; i++) {
            float v = __int_as_float(cv[i].y);
            const __half2* hp = reinterpret_cast<const __half2*>(&xv[i]);
            float2 f0 = __half22float2(hp[0]);
            float2 f1 = __half22float2(hp[1]);
            float2 f2 = __half22float2(hp[2]);
            float2 f3 = __half22float2(hp[3]);
            s[0] = fmaf(v, f0.x, s[0]); s[1] = fmaf(v, f0.y, s[1]);
            s[2] = fmaf(v, f1.x, s[2]); s[3] = fmaf(v, f1.y, s[3]);
            s[4] = fmaf(v, f2.x, s[4]); s[5] = fmaf(v, f2.y, s[5]);
            s[6] = fmaf(v, f3.x, s[6]); s[7] = fmaf(v, f3.y, s[7]);
        }
        j += 8;
    }
    for (; j < deg; j += 2) {
        int e = j + ehalf;
        int2 cv = (e < deg) ? __ldg(scv + start + e) : make_int2(0, 0);
        float v = __int_as_float(cv.y);
        uint4 xv = __ldg(reinterpret_cast<const uint4*>(x + (size_t)cv.x * EMB) + fc);
        const __half2* hp = reinterpret_cast<const __half2*>(&xv);
        float2 f0 = __half22float2(hp[0]);
        float2 f1 = __half22float2(hp[1]);
        float2 f2 = __half22float2(hp[2]);
        float2 f3 = __half22float2(hp[3]);
        s[0] = fmaf(v, f0.x, s[0]); s[1] = fmaf(v, f0.y, s[1]);
        s[2] = fmaf(v, f1.x, s[2]); s[3] = fmaf(v, f1.y, s[3]);
        s[4] = fmaf(v, f2.x, s[4]); s[5] = fmaf(v, f2.y, s[5]);
        s[6] = fmaf(v, f3.x, s[6]); s[7] = fmaf(v, f3.y, s[7]);
    }

#pragma unroll
    for (int i = 0; i < 8; i++)
        s[i] += __shfl_xor_sync(0xFFFFFFFFu, s[i], 16);

    float ss = s[0] * s[0] + s[1] * s[1] + s[2] * s[2] + s[3] * s[3]
             + s[4] * s[4] + s[5] * s[5] + s[6] * s[6] + s[7] * s[7];
#pragma unroll
    for (int o = 1; o < 16; o <<= 1) ss += __shfl_xor_sync(0xFFFFFFFFu, ss, o);
    float inv = 1.f / fmaxf(sqrtf(ss), 1e-12f);

    if (unext) {
        if (ehalf == 0) {
            __half2 h0 = __floats2half2_rn(s[0], s[1]);
            __half2 h1 = __floats2half2_rn(s[2], s[3]);
            __half2 h2 = __floats2half2_rn(s[4], s[5]);
            __half2 h3 = __floats2half2_rn(s[6], s[7]);
            uint4 hw;
            hw.x = h2u(h0); hw.y = h2u(h1);
            hw.z = h2u(h2); hw.w = h2u(h3);
            *(reinterpret_cast<uint4*>(unext + (size_t)row * EMB) + fc) = hw;
        }
        if (lane == 0) invout[row] = inv;
    } else {
        float ip = __ldg(invprev + row);
        int fbase = fc * 8 + ehalf * 4;
        const float* sp = s + ehalf * 4;
        uint2 raw = __ldg(reinterpret_cast<const uint2*>(x + (size_t)row * EMB + fbase));
        __half2 u1h0 = *reinterpret_cast<__half2*>(&raw.x);
        __half2 u1h1 = *reinterpret_cast<__half2*>(&raw.y);
        float2 u1f0 = __half22float2(u1h0);
        float2 u1f1 = __half22float2(u1h1);
        float4* ap = reinterpret_cast<float4*>(acc + (size_t)row * EMB + fbase);
        float4 a = *ap;
        a.x = fmaf(ip, u1f0.x, fmaf(sp[0], inv, a.x));
        a.y = fmaf(ip, u1f0.y, fmaf(sp[1], inv, a.y));
        a.z = fmaf(ip, u1f1.x, fmaf(sp[2], inv, a.z));
        a.w = fmaf(ip, u1f1.y, fmaf(sp[3], inv, a.w));
        *ap = a;
    }
}

// ---------------- launch -----------------------------------------------------
static cudaStream_t g_side = nullptr;
static cudaEvent_t  g_evFork = nullptr, g_evGate = nullptr;

extern "C" void kernel_launch(void* const* d_in, const int* in_sizes, int n_in,
                              void* d_out, int out_size) {
    const float* emb  = (const float*)d_in[0];
    const float* W    = (const float*)d_in[1];
    const float* bias = (const float*)d_in[2];
    const int*   rows = (const int*)  d_in[3];
    const int*   cols = (const int*)  d_in[4];
    const float* vals = (const float*)d_in[5];

    int n   = in_sizes[0] / EMB;
    int nnz = in_sizes[3];
    float* acc = (float*)d_out;

    __half *bufA, *bufB;
    int *csrws, *rs, *cur;
    int2 *scv;
    uint4 *wfrag;
    float *invb;
    cudaGetSymbolAddress((void**)&bufA,  g_bufA);
    cudaGetSymbolAddress((void**)&bufB,  g_bufB);
    cudaGetSymbolAddress((void**)&csrws, g_csrws);
    cudaGetSymbolAddress((void**)&rs,    g_rs);
    cudaGetSymbolAddress((void**)&cur,   g_cur);
    cudaGetSymbolAddress((void**)&scv,   g_scv);
    cudaGetSymbolAddress((void**)&wfrag, g_wfrag);
    cudaGetSymbolAddress((void**)&invb,  g_inv);

    int* cnt = csrws;
    unsigned long long* stat = (unsigned long long*)(csrws + n);
    int* ticket = csrws + n + 52;
    int* done   = csrws + n + 53;

    if (!g_side) {   // resource init only (first, uncaptured call); no work cached
        cudaStreamCreateWithFlags(&g_side, cudaStreamNonBlocking);
        cudaEventCreateWithFlags(&g_evFork, cudaEventDisableTiming);
        cudaEventCreateWithFlags(&g_evGate, cudaEventDisableTiming);
    }

    int smem_bytes = 64 * HSTRIDE * sizeof(__half);   // 17.4 KB
    cudaFuncSetAttribute(gate_mma_kernel,
                         cudaFuncAttributeMaxDynamicSharedMemorySize, smem_bytes);

    // K1 (main): W-fragment transpose (gate's only dependency besides emb)
    wtrans_kernel<<<8, 256>>>(W, wfrag);

    // fork: gate on side stream, overlapped with CSR build on main
    cudaEventRecord(g_evFork, 0);
    cudaStreamWaitEvent(g_side, g_evFork, 0);
    gate_mma_kernel<<<(n + 63) / 64, 256, smem_bytes, g_side>>>(
        emb, wfrag, bias, bufA, acc, n);
    cudaEventRecord(g_evGate, g_side);

    // main: hist -> scan -> scatter
    hist_kernel<<<(nnz + 255) / 256, 256>>>(rows, cnt, nnz);
    int nb = (n + 4095) / 4096;
    scan_kernel<<<nb, 1024>>>(cnt, rs, cur, stat, ticket, done, n);
    scatter_kernel<<<(nnz + 255) / 256, 256>>>(rows, cols, vals, cur, scv, nnz);

    // join: spmm needs bufA (gate) + scv (scatter)
    cudaStreamWaitEvent(0, g_evGate, 0);

    unsigned spmm_blocks = (unsigned)(((size_t)n * 32 + 255) / 256);
    spmm_fused_kernel<<<spmm_blocks, 256>>>(rs, scv, bufA, bufB, invb, nullptr, nullptr, n);
    spmm_fused_kernel<<<spmm_blocks, 256>>>(rs, scv, bufB, nullptr, nullptr, invb, acc, n);
}